// round 6
// baseline (speedup 1.0000x reference)
#include <cuda_runtime.h>
#include <cuda_bf16.h>
#include <math.h>
#include <stdint.h>

// Problem constants
#define BATCH 4
#define TT    4096
#define DD    1024
#define LATD  1024
#define NH    8
#define DHD   128
#define TSPLIT 16
#define TCHUNK (TT / TSPLIT)   // 256

typedef long long ll;

// ---------------- scratch (device globals; no allocation allowed) ----------------
__device__ float g_Q[(size_t)BATCH * TT * LATD];
__device__ float g_K[(size_t)BATCH * TT * LATD];
__device__ float g_V[(size_t)BATCH * TT * DD];
__device__ float g_Z[(size_t)BATCH * DD * DD];           // fused Kvn@Wout, per-batch 1024x1024
__device__ float g_Kvpart[(size_t)TSPLIT * 32 * 128 * 128];
__device__ float g_Ksumpart[(size_t)TSPLIT * 32 * 128];
__device__ float g_Kvn[(size_t)32 * 128 * 128];
// bf16 split buffers
__device__ __nv_bfloat16 g_Ahi[(size_t)BATCH * TT * DD];
__device__ __nv_bfloat16 g_Alo[(size_t)BATCH * TT * DD];
__device__ __nv_bfloat16 g_Bhi[(size_t)BATCH * DD * DD];  // transposed weights [N][K]
__device__ __nv_bfloat16 g_Blo[(size_t)BATCH * DD * DD];

// ============================ PTX helpers (base sm_100-safe) ============================
__device__ __forceinline__ uint32_t smem_u32(const void* p) {
    uint32_t a;
    asm("{ .reg .u64 t; cvta.to.shared.u64 t, %1; cvt.u32.u64 %0, t; }" : "=r"(a) : "l"(p));
    return a;
}
#define CP_ASYNC16(s, g) asm volatile("cp.async.cg.shared.global [%0], [%1], 16;" :: "r"(s), "l"(g))
#define CP_COMMIT() asm volatile("cp.async.commit_group;" ::: "memory")
#define CP_WAIT(n)  asm volatile("cp.async.wait_group %0;" :: "n"(n) : "memory")

#define LDSM_X4(r0, r1, r2, r3, a) \
    asm volatile("ldmatrix.sync.aligned.m8n8.x4.shared.b16 {%0,%1,%2,%3}, [%4];" \
                 : "=r"(r0), "=r"(r1), "=r"(r2), "=r"(r3) : "r"(a))

#define MMA_BF16(c, a, b) \
    asm volatile("mma.sync.aligned.m16n8k16.row.col.f32.bf16.bf16.f32 " \
                 "{%0,%1,%2,%3}, {%4,%5,%6,%7}, {%8,%9}, {%0,%1,%2,%3};" \
                 : "+f"((c)[0]), "+f"((c)[1]), "+f"((c)[2]), "+f"((c)[3]) \
                 : "r"((a)[0]), "r"((a)[1]), "r"((a)[2]), "r"((a)[3]), \
                   "r"((b)[0]), "r"((b)[1]))

// ============================ split-bf16 HMMA GEMM ============================
// C[M,1024] = A[M,1024] x Bt[1024,1024]^T  (Bt N-major => "col" operand)
// 3-term: AhBh + AlBh + AhBl, fp32 accum.
// CTA tile 256x128, 8 warps (warp tile 64x64), K-chunk 64, 2-stage cp.async.
#define NKC 16                  // 1024 / 64
#define ROWB 144                // padded row stride bytes (128B data + 16B pad)
#define ASUB (256 * ROWB)       // 36864 B
#define BSUB (128 * ROWB)       // 18432 B
#define STAGEB (2 * ASUB + 2 * BSUB)   // 110592 B
#define GEMM_SMEM (2 * STAGEB)         // 221184 B

__global__ __launch_bounds__(256, 1) void hmma_gemm_kernel(
    const __nv_bfloat16* __restrict__ Ah, const __nv_bfloat16* __restrict__ Al,
    const __nv_bfloat16* __restrict__ Bh, const __nv_bfloat16* __restrict__ Bl,
    float* __restrict__ C, ll aZ, ll bZ, ll cZ)
{
    extern __shared__ char dsm[];
    const uint32_t sbase = smem_u32(dsm);

    const int tid = threadIdx.x;
    const int wid = tid >> 5, lane = tid & 31;
    const int wm = wid & 3;         // 0..3 -> 64-row quarter of 256
    const int wn = wid >> 2;        // 0..1 -> 64-col half of 128
    const int m0 = blockIdx.y * 256;
    const int n0 = blockIdx.x * 128;
    const int z  = blockIdx.z;

    const __nv_bfloat16* srcA[2] = { Ah + (ll)z * aZ + (ll)m0 * 1024,
                                     Al + (ll)z * aZ + (ll)m0 * 1024 };
    const __nv_bfloat16* srcB[2] = { Bh + (ll)z * bZ + (ll)n0 * 1024,
                                     Bl + (ll)z * bZ + (ll)n0 * 1024 };
    C += (ll)z * cZ;

    // ---- stage loader ----
    auto load_stage = [&](int s, int kc) {
        uint32_t st = sbase + s * STAGEB;
        const int k0 = kc * 64;
#pragma unroll
        for (int sub = 0; sub < 2; sub++) {          // Ah, Al: 256 rows
            const __nv_bfloat16* g = srcA[sub] + k0;
            uint32_t base = st + sub * ASUB;
#pragma unroll
            for (int u = 0; u < 8; u++) {
                int idx = tid + u * 256;             // 0..2047
                int r = idx >> 3, ch = idx & 7;
                CP_ASYNC16(base + r * ROWB + ch * 16, g + (ll)r * 1024 + ch * 8);
            }
        }
#pragma unroll
        for (int sub = 0; sub < 2; sub++) {          // Bh, Bl: 128 rows
            const __nv_bfloat16* g = srcB[sub] + k0;
            uint32_t base = st + 2 * ASUB + sub * BSUB;
#pragma unroll
            for (int u = 0; u < 4; u++) {
                int idx = tid + u * 256;             // 0..1023
                int r = idx >> 3, ch = idx & 7;
                CP_ASYNC16(base + r * ROWB + ch * 16, g + (ll)r * 1024 + ch * 8);
            }
        }
    };

    float acc[4][8][4];
#pragma unroll
    for (int i = 0; i < 4; i++)
#pragma unroll
        for (int j = 0; j < 8; j++)
#pragma unroll
            for (int v = 0; v < 4; v++) acc[i][j][v] = 0.f;

    const int arow_l = lane & 15, aseg = lane >> 4;
    const int brow_l = (lane & 7) + ((lane >> 4) << 3), bseg = (lane >> 3) & 1;

    load_stage(0, 0); CP_COMMIT();

    for (int kc = 0; kc < NKC; kc++) {
        const int s = kc & 1;
        if (kc + 1 < NKC) { load_stage(s ^ 1, kc + 1); CP_COMMIT(); CP_WAIT(1); }
        else               CP_WAIT(0);
        __syncthreads();

        const uint32_t st = sbase + s * STAGEB;
        const uint32_t sAh = st, sAl = st + ASUB, sBh = st + 2 * ASUB, sBl = st + 2 * ASUB + BSUB;

#pragma unroll
        for (int ks = 0; ks < 4; ks++) {
            uint32_t ah[4][4], al[4][4], bh[8][2], bl[8][2];
#pragma unroll
            for (int mi = 0; mi < 4; mi++) {
                uint32_t off = (uint32_t)((wm * 64 + mi * 16 + arow_l) * ROWB + ks * 32 + aseg * 16);
                LDSM_X4(ah[mi][0], ah[mi][1], ah[mi][2], ah[mi][3], sAh + off);
                LDSM_X4(al[mi][0], al[mi][1], al[mi][2], al[mi][3], sAl + off);
            }
#pragma unroll
            for (int np = 0; np < 4; np++) {
                uint32_t off = (uint32_t)((wn * 64 + np * 16 + brow_l) * ROWB + ks * 32 + bseg * 16);
                LDSM_X4(bh[np*2][0], bh[np*2][1], bh[np*2+1][0], bh[np*2+1][1], sBh + off);
                LDSM_X4(bl[np*2][0], bl[np*2][1], bl[np*2+1][0], bl[np*2+1][1], sBl + off);
            }
#pragma unroll
            for (int mi = 0; mi < 4; mi++)
#pragma unroll
                for (int nt = 0; nt < 8; nt++) {
                    MMA_BF16(acc[mi][nt], ah[mi], bh[nt]);
                    MMA_BF16(acc[mi][nt], al[mi], bh[nt]);
                    MMA_BF16(acc[mi][nt], ah[mi], bl[nt]);
                }
        }
        __syncthreads();
    }

    // epilogue
    const int g = lane >> 2, tig = lane & 3;
#pragma unroll
    for (int mi = 0; mi < 4; mi++) {
        int row = m0 + wm * 64 + mi * 16 + g;
#pragma unroll
        for (int nt = 0; nt < 8; nt++) {
            int col = n0 + wn * 64 + nt * 8 + tig * 2;
            *(float2*)&C[(ll)row * 1024 + col]       = make_float2(acc[mi][nt][0], acc[mi][nt][1]);
            *(float2*)&C[(ll)(row + 8) * 1024 + col] = make_float2(acc[mi][nt][2], acc[mi][nt][3]);
        }
    }
}

// ============================ converters ============================
__global__ __launch_bounds__(256) void convA_kernel(const float* __restrict__ x,
                                                    __nv_bfloat16* __restrict__ hi,
                                                    __nv_bfloat16* __restrict__ lo, int n4)
{
    int i = blockIdx.x * 256 + threadIdx.x;
    if (i >= n4) return;
    float4 v = *(const float4*)&x[(ll)i * 4];
    __nv_bfloat16 h0 = __float2bfloat16(v.x), h1 = __float2bfloat16(v.y);
    __nv_bfloat16 h2 = __float2bfloat16(v.z), h3 = __float2bfloat16(v.w);
    __nv_bfloat16 l0 = __float2bfloat16(v.x - __bfloat162float(h0));
    __nv_bfloat16 l1 = __float2bfloat16(v.y - __bfloat162float(h1));
    __nv_bfloat16 l2 = __float2bfloat16(v.z - __bfloat162float(h2));
    __nv_bfloat16 l3 = __float2bfloat16(v.w - __bfloat162float(h3));
    *(__nv_bfloat162*)&hi[(ll)i * 4]     = __nv_bfloat162(h0, h1);
    *(__nv_bfloat162*)&hi[(ll)i * 4 + 2] = __nv_bfloat162(h2, h3);
    *(__nv_bfloat162*)&lo[(ll)i * 4]     = __nv_bfloat162(l0, l1);
    *(__nv_bfloat162*)&lo[(ll)i * 4 + 2] = __nv_bfloat162(l2, l3);
}

// weight transpose + split, batched: W[z][1024,1024] row-major -> WT[z][n][k] hi/lo
__global__ __launch_bounds__(1024) void convWT_kernel(const float* __restrict__ W,
                                                      __nv_bfloat16* __restrict__ hi,
                                                      __nv_bfloat16* __restrict__ lo,
                                                      ll wZ)
{
    __shared__ float ts[32][33];
    const ll zo = (ll)blockIdx.z * wZ;
    int tx = threadIdx.x & 31, ty = threadIdx.x >> 5;
    int k0 = blockIdx.y * 32, n0 = blockIdx.x * 32;
    ts[ty][tx] = W[zo + (ll)(k0 + ty) * 1024 + n0 + tx];
    __syncthreads();
    float v = ts[tx][ty];   // = W[k0+tx][n0+ty]
    __nv_bfloat16 h = __float2bfloat16(v);
    __nv_bfloat16 l = __float2bfloat16(v - __bfloat162float(h));
    hi[zo + (ll)(n0 + ty) * 1024 + k0 + tx] = h;
    lo[zo + (ll)(n0 + ty) * 1024 + k0 + tx] = l;
}

// ---------------- softmax over 128-wide head slices of Q, emit bf16 hi/lo split ----------------
__global__ __launch_bounds__(256) void softmax128_split_kernel(const float* __restrict__ Q,
                                                               __nv_bfloat16* __restrict__ hi,
                                                               __nv_bfloat16* __restrict__ lo)
{
    ll row = ((ll)blockIdx.x << 3) + (threadIdx.x >> 5);
    int lane = threadIdx.x & 31;
    const float* p = Q + (row << 7);
    float4 v = *(const float4*)&p[lane << 2];
    float m = fmaxf(fmaxf(v.x, v.y), fmaxf(v.z, v.w));
#pragma unroll
    for (int o = 16; o > 0; o >>= 1) m = fmaxf(m, __shfl_xor_sync(0xffffffffu, m, o));
    float4 e;
    e.x = expf(v.x - m); e.y = expf(v.y - m);
    e.z = expf(v.z - m); e.w = expf(v.w - m);
    float s = e.x + e.y + e.z + e.w;
#pragma unroll
    for (int o = 16; o > 0; o >>= 1) s += __shfl_xor_sync(0xffffffffu, s, o);
    float inv = 1.f / s;
    e.x *= inv; e.y *= inv; e.z *= inv; e.w *= inv;
    __nv_bfloat16 h0 = __float2bfloat16(e.x), h1 = __float2bfloat16(e.y);
    __nv_bfloat16 h2 = __float2bfloat16(e.z), h3 = __float2bfloat16(e.w);
    __nv_bfloat16 l0 = __float2bfloat16(e.x - __bfloat162float(h0));
    __nv_bfloat16 l1 = __float2bfloat16(e.y - __bfloat162float(h1));
    __nv_bfloat16 l2 = __float2bfloat16(e.z - __bfloat162float(h2));
    __nv_bfloat16 l3 = __float2bfloat16(e.w - __bfloat162float(h3));
    ll o4 = (row << 7) + (lane << 2);
    *(__nv_bfloat162*)&hi[o4]     = __nv_bfloat162(h0, h1);
    *(__nv_bfloat162*)&hi[o4 + 2] = __nv_bfloat162(h2, h3);
    *(__nv_bfloat162*)&lo[o4]     = __nv_bfloat162(l0, l1);
    *(__nv_bfloat162*)&lo[o4 + 2] = __nv_bfloat162(l2, l3);
}

// ---------------- fp32 tiled GEMM (small Z = Kvn @ Wout_h) ----------------
#define BM 128
#define BN 128
#define BK 16
__global__ __launch_bounds__(256) void sgemm_kernel(
    const float* __restrict__ A, const float* __restrict__ Bm, float* __restrict__ C,
    int K, int lda, int ldb, int ldc,
    ll aHi, ll aLo, ll bHi, ll bLo, ll cHi, ll cLo)
{
    const int z = blockIdx.z;
    A  += (ll)(z >> 3) * aHi + (ll)(z & 7) * aLo;
    Bm += (ll)(z >> 3) * bHi + (ll)(z & 7) * bLo;
    C  += (ll)(z >> 3) * cHi + (ll)(z & 7) * cLo;

    __shared__ float As[BK][BM];
    __shared__ float Bs[BK][BN];
    const int tid = threadIdx.x;
    const int ty = tid >> 4, tx = tid & 15;
    const int m0 = blockIdx.y * BM, n0 = blockIdx.x * BN;

    float acc[8][8];
#pragma unroll
    for (int i = 0; i < 8; i++)
#pragma unroll
        for (int j = 0; j < 8; j++) acc[i][j] = 0.f;

    for (int k0 = 0; k0 < K; k0 += BK) {
#pragma unroll
        for (int u = 0; u < 2; u++) {
            int idx = tid + u * 256;
            int r = idx >> 2, c4 = (idx & 3) << 2;
            float4 v = *(const float4*)&A[(ll)(m0 + r) * lda + k0 + c4];
            As[c4 + 0][r] = v.x; As[c4 + 1][r] = v.y;
            As[c4 + 2][r] = v.z; As[c4 + 3][r] = v.w;
        }
#pragma unroll
        for (int u = 0; u < 2; u++) {
            int idx = tid + u * 256;
            int r = idx >> 5, c4 = (idx & 31) << 2;
            *(float4*)&Bs[r][c4] = *(const float4*)&Bm[(ll)(k0 + r) * ldb + n0 + c4];
        }
        __syncthreads();
#pragma unroll
        for (int k = 0; k < BK; k++) {
            float4 a0 = *(const float4*)&As[k][ty * 8];
            float4 a1 = *(const float4*)&As[k][ty * 8 + 4];
            float4 b0 = *(const float4*)&Bs[k][tx * 8];
            float4 b1 = *(const float4*)&Bs[k][tx * 8 + 4];
            float a[8] = {a0.x,a0.y,a0.z,a0.w,a1.x,a1.y,a1.z,a1.w};
            float b[8] = {b0.x,b0.y,b0.z,b0.w,b1.x,b1.y,b1.z,b1.w};
#pragma unroll
            for (int i = 0; i < 8; i++)
#pragma unroll
                for (int j = 0; j < 8; j++) acc[i][j] += a[i] * b[j];
        }
        __syncthreads();
    }
#pragma unroll
    for (int i = 0; i < 8; i++) {
        int r = m0 + ty * 8 + i;
#pragma unroll
        for (int j = 0; j < 8; j += 4) {
            *(float4*)&C[(ll)r * ldc + n0 + tx * 8 + j] =
                make_float4(acc[i][j], acc[i][j+1], acc[i][j+2], acc[i][j+3]);
        }
    }
}

// ---------------- Kv partial over 256-token chunks ----------------
__global__ __launch_bounds__(256) void kv_partial_kernel(void)
{
    const int z  = blockIdx.x;
    const int tc = blockIdx.y;
    const int b = z >> 3, h = z & 7;
    const float* Ab = g_K + (ll)b * TT * LATD + h * DHD;
    const float* Bb = g_V + (ll)b * TT * DD   + h * DHD;

    __shared__ float As[16][128];
    __shared__ float Bs[16][128];
    const int tid = threadIdx.x;
    const int ty = tid >> 4, tx = tid & 15;
    float acc[8][8];
#pragma unroll
    for (int i = 0; i < 8; i++)
#pragma unroll
        for (int j = 0; j < 8; j++) acc[i][j] = 0.f;
    float ksum = 0.f;

    const int t0 = tc * TCHUNK;
    for (int tt = 0; tt < TCHUNK; tt += 16) {
#pragma unroll
        for (int u = 0; u < 2; u++) {
            int idx = tid + u * 256;
            int k = idx >> 5, i4 = (idx & 31) << 2;
            ll trow = (ll)(t0 + tt + k);
            float4 va = *(const float4*)&Ab[trow * LATD + i4];
            As[k][i4 + 0] = expf(va.x); As[k][i4 + 1] = expf(va.y);
            As[k][i4 + 2] = expf(va.z); As[k][i4 + 3] = expf(va.w);
            *(float4*)&Bs[k][i4] = *(const float4*)&Bb[trow * DD + i4];
        }
        __syncthreads();
        if (tid < 128) {
#pragma unroll
            for (int k = 0; k < 16; k++) ksum += As[k][tid];
        }
#pragma unroll
        for (int k = 0; k < 16; k++) {
            float4 a0 = *(const float4*)&As[k][ty * 8];
            float4 a1 = *(const float4*)&As[k][ty * 8 + 4];
            float4 b0 = *(const float4*)&Bs[k][tx * 8];
            float4 b1 = *(const float4*)&Bs[k][tx * 8 + 4];
            float a[8] = {a0.x,a0.y,a0.z,a0.w,a1.x,a1.y,a1.z,a1.w};
            float b[8] = {b0.x,b0.y,b0.z,b0.w,b1.x,b1.y,b1.z,b1.w};
#pragma unroll
            for (int i = 0; i < 8; i++)
#pragma unroll
                for (int j = 0; j < 8; j++) acc[i][j] += a[i] * b[j];
        }
        __syncthreads();
    }

    float* Cp = g_Kvpart + ((ll)tc * 32 + z) * (128 * 128);
#pragma unroll
    for (int i = 0; i < 8; i++) {
        int r = ty * 8 + i;
#pragma unroll
        for (int j = 0; j < 8; j += 4) {
            *(float4*)&Cp[r * 128 + tx * 8 + j] =
                make_float4(acc[i][j], acc[i][j+1], acc[i][j+2], acc[i][j+3]);
        }
    }
    if (tid < 128) g_Ksumpart[((ll)tc * 32 + z) * 128 + tid] = ksum;
}

__global__ __launch_bounds__(128) void kv_reduce_norm_kernel(void)
{
    const int j  = threadIdx.x;
    const int zi = blockIdx.x;
    const int z = zi >> 7, i = zi & 127;
    float kv = 0.f, s = 0.f;
#pragma unroll
    for (int tc = 0; tc < TSPLIT; tc++) {
        kv += g_Kvpart[((ll)tc * 32 + z) * 16384 + i * 128 + j];
        s  += g_Ksumpart[((ll)tc * 32 + z) * 128 + i];
    }
    g_Kvn[(ll)z * 16384 + i * 128 + j] = kv / s;
}

// ---------------- launch ----------------
extern "C" void kernel_launch(void* const* d_in, const int* in_sizes, int n_in,
                              void* d_out, int out_size)
{
    const float* query = (const float*)d_in[0];
    const float* key   = (const float*)d_in[1];
    const float* wq    = (const float*)d_in[2];
    const float* wk    = (const float*)d_in[3];
    const float* wv    = (const float*)d_in[4];
    const float* wproj = (const float*)d_in[5];
    float* out = (float*)d_out;

    float *Q, *K, *V, *Z, *Kvn;
    __nv_bfloat16 *Ahi, *Alo, *Bhi, *Blo;
    cudaGetSymbolAddress((void**)&Q,   g_Q);
    cudaGetSymbolAddress((void**)&K,   g_K);
    cudaGetSymbolAddress((void**)&V,   g_V);
    cudaGetSymbolAddress((void**)&Z,   g_Z);
    cudaGetSymbolAddress((void**)&Kvn, g_Kvn);
    cudaGetSymbolAddress((void**)&Ahi, g_Ahi);
    cudaGetSymbolAddress((void**)&Alo, g_Alo);
    cudaGetSymbolAddress((void**)&Bhi, g_Bhi);
    cudaGetSymbolAddress((void**)&Blo, g_Blo);

    cudaFuncSetAttribute(hmma_gemm_kernel, cudaFuncAttributeMaxDynamicSharedMemorySize, GEMM_SMEM);

    const int MBT = BATCH * TT;                 // 16384
    const int actN4 = MBT * DD / 4;
    dim3 gconvA((actN4 + 255) / 256), bconvA(256);
    dim3 gconvW(32, 32, 1), bconvW(1024);
    dim3 ggemm(8, 64, 1), bgemm(256);           // 256-row tiles: 16384/256 = 64

    // ---- Q = query * wq ----
    convWT_kernel<<<gconvW, bconvW>>>(wq, Bhi, Blo, 0);
    convA_kernel<<<gconvA, bconvA>>>(query, Ahi, Alo, actN4);
    hmma_gemm_kernel<<<ggemm, bgemm, GEMM_SMEM>>>(Ahi, Alo, Bhi, Blo, Q, 0, 0, 0);

    // ---- K = key * wk ; V = key * wv (key converted once) ----
    convA_kernel<<<gconvA, bconvA>>>(key, Ahi, Alo, actN4);
    convWT_kernel<<<gconvW, bconvW>>>(wk, Bhi, Blo, 0);
    hmma_gemm_kernel<<<ggemm, bgemm, GEMM_SMEM>>>(Ahi, Alo, Bhi, Blo, K, 0, 0, 0);
    convWT_kernel<<<gconvW, bconvW>>>(wv, Bhi, Blo, 0);
    hmma_gemm_kernel<<<ggemm, bgemm, GEMM_SMEM>>>(Ahi, Alo, Bhi, Blo, V, 0, 0, 0);

    // ---- softmax(Q) -> bf16 hi/lo split directly (A operand of final GEMM) ----
    softmax128_split_kernel<<<(MBT * NH) / 8, 256>>>(Q, Ahi, Alo);

    // ---- Kv aggregation + normalize -> Kvn[z=b*8+h][l][d] ----
    kv_partial_kernel<<<dim3(32, TSPLIT, 1), 256>>>();
    kv_reduce_norm_kernel<<<dim3(32 * 128, 1, 1), 128>>>();

    // ---- Z[b, h*128+l, n] = sum_d Kvn[b,h,l,d] * Wout[h*128+d, n] ----
    dim3 gz(8, 1, 32);
    sgemm_kernel<<<gz, 256>>>(Kvn, wproj, Z, 128, 128, 1024, 1024,
                              (ll)8 * 16384, 16384,
                              0, 131072,
                              1048576, 131072);

    // ---- out[b] = Qs[b] @ Z[b] ----
    dim3 gconvWZ(32, 32, 4);
    convWT_kernel<<<gconvWZ, bconvW>>>(Z, Bhi, Blo, 1048576);
    dim3 gout(8, 16, 4);                        // 4096/256 = 16 row tiles per batch
    hmma_gemm_kernel<<<gout, bgemm, GEMM_SMEM>>>(Ahi, Alo, Bhi, Blo, out,
                                                 (ll)TT * DD, (ll)DD * DD, (ll)TT * DD);
}

// round 7
// speedup vs baseline: 1.3836x; 1.3836x over previous
#include <cuda_runtime.h>
#include <cuda_fp16.h>
#include <math.h>
#include <stdint.h>

// Problem constants
#define BATCH 4
#define TT    4096
#define DD    1024
#define LATD  1024
#define NH    8
#define DHD   128
#define TSPLIT 16
#define TCHUNK (TT / TSPLIT)   // 256

typedef long long ll;

// ---------------- scratch (device globals; no allocation allowed) ----------------
__device__ float g_Q[(size_t)BATCH * TT * LATD];
__device__ float g_K[(size_t)BATCH * TT * LATD];
__device__ float g_V[(size_t)BATCH * TT * DD];
__device__ float g_Z[(size_t)BATCH * DD * DD];
__device__ float g_Kvpart[(size_t)TSPLIT * 32 * 128 * 128];
__device__ float g_Ksumpart[(size_t)TSPLIT * 32 * 128];
__device__ float g_Kvn[(size_t)32 * 128 * 128];
// fp16 operand buffers
__device__ __half g_Aq[(size_t)BATCH * TT * DD];   // query fp16, later softmax(Q) fp16
__device__ __half g_Ak[(size_t)BATCH * TT * DD];   // key fp16
__device__ __half g_Bh[(size_t)4 * DD * DD];       // weight^T hi: slots wq,wk,wv | Z(4 batches)
__device__ __half g_Bl[(size_t)4 * DD * DD];       // weight^T lo

// ============================ PTX helpers ============================
__device__ __forceinline__ uint32_t smem_u32(const void* p) {
    uint32_t a;
    asm("{ .reg .u64 t; cvta.to.shared.u64 t, %1; cvt.u32.u64 %0, t; }" : "=r"(a) : "l"(p));
    return a;
}
#define CP_ASYNC16(s, g) asm volatile("cp.async.cg.shared.global [%0], [%1], 16;" :: "r"(s), "l"(g))
#define CP_COMMIT() asm volatile("cp.async.commit_group;" ::: "memory")
#define CP_WAIT(n)  asm volatile("cp.async.wait_group %0;" :: "n"(n) : "memory")

#define LDSM_X4(r0, r1, r2, r3, a) \
    asm volatile("ldmatrix.sync.aligned.m8n8.x4.shared.b16 {%0,%1,%2,%3}, [%4];" \
                 : "=r"(r0), "=r"(r1), "=r"(r2), "=r"(r3) : "r"(a))

#define MMA_F16(c, a, b) \
    asm volatile("mma.sync.aligned.m16n8k16.row.col.f32.f16.f16.f32 " \
                 "{%0,%1,%2,%3}, {%4,%5,%6,%7}, {%8,%9}, {%0,%1,%2,%3};" \
                 : "+f"((c)[0]), "+f"((c)[1]), "+f"((c)[2]), "+f"((c)[3]) \
                 : "r"((a)[0]), "r"((a)[1]), "r"((a)[2]), "r"((a)[3]), \
                   "r"((b)[0]), "r"((b)[1]))

// ============================ persistent 2-term fp16 HMMA GEMM ============================
// C_tile[128,128] = A[128rows,K=1024] x (Bh+Bl)[128rows,K=1024]^T   (B N-major "col")
// Tile 128x128, 4 warps (64x64 each), K-chunk 64, 2-stage cp.async, 2 CTAs/SM.
#define NKC 16
#define ROWB 144                 // 128B data + 16B pad
#define SUBT (128 * ROWB)        // 18432
#define STAGEB (3 * SUBT)        // A, Bh, Bl = 55296
#define GEMM_SMEM (2 * STAGEB)   // 110592

struct GemmJobs {
    const __half* A[3];
    const __half* Bh[3];
    const __half* Bl[3];
    float*        C[3];
    int total;       // total tiles (njobs * 1024)
    int bShift;      // -1, or m_idx>>bShift selects B batch
    ll  bStride;     // element stride between B batches
};

__global__ __launch_bounds__(128, 2) void phmma_kernel(GemmJobs J)
{
    extern __shared__ char dsm[];
    const uint32_t sbase = smem_u32(dsm);
    const int tid = threadIdx.x;
    const int wid = tid >> 5, lane = tid & 31;
    const int wm = wid & 1, wn = wid >> 1;
    const int arow_l = lane & 15, aseg = lane >> 4;
    const int brow_l = (lane & 7) + ((lane >> 4) << 3), bseg = (lane >> 3) & 1;
    const int g = lane >> 2, tig = lane & 3;

    for (int t = blockIdx.x; t < J.total; t += gridDim.x) {
        const int job = t >> 10;            // 1024 tiles per job
        const int rem = t & 1023;
        const int mI = rem >> 3, nI = rem & 7;

        const __half* Ap  = J.A[job]  + (ll)mI * 131072;
        const __half* Bhp = J.Bh[job];
        const __half* Blp = J.Bl[job];
        if (J.bShift >= 0) {
            ll bo = (ll)(mI >> J.bShift) * J.bStride;
            Bhp += bo; Blp += bo;
        }
        Bhp += (ll)nI * 131072;
        Blp += (ll)nI * 131072;
        float* Cp = J.C[job] + (ll)mI * 131072 + nI * 128;

        float acc[4][8][4];
#pragma unroll
        for (int i = 0; i < 4; i++)
#pragma unroll
            for (int j = 0; j < 8; j++)
#pragma unroll
                for (int v = 0; v < 4; v++) acc[i][j][v] = 0.f;

        // ---- stage loader: A, Bh, Bl each 128 rows x 128B ----
        auto load_stage = [&](int s, int kc) {
            uint32_t st = sbase + s * STAGEB;
            const int k0 = kc * 64;
            const __half* gs[3] = { Ap + k0, Bhp + k0, Blp + k0 };
#pragma unroll
            for (int sub = 0; sub < 3; sub++) {
                const __half* gg = gs[sub];
                uint32_t base = st + sub * SUBT;
#pragma unroll
                for (int u = 0; u < 8; u++) {
                    int idx = tid + u * 128;      // 0..1023
                    int r = idx >> 3, ch = idx & 7;
                    CP_ASYNC16(base + r * ROWB + ch * 16, gg + (ll)r * 1024 + ch * 8);
                }
            }
            CP_COMMIT();
        };

        load_stage(0, 0);
        for (int kc = 0; kc < NKC; kc++) {
            const int s = kc & 1;
            if (kc + 1 < NKC) { load_stage(s ^ 1, kc + 1); CP_WAIT(1); }
            else               CP_WAIT(0);
            __syncthreads();

            const uint32_t st = sbase + s * STAGEB;
            const uint32_t sA = st, sBh = st + SUBT, sBl = st + 2 * SUBT;

#pragma unroll
            for (int ks = 0; ks < 4; ks++) {
                uint32_t a[4][4], bh[8][2], bl[8][2];
#pragma unroll
                for (int mi = 0; mi < 4; mi++) {
                    uint32_t off = (uint32_t)((wm * 64 + mi * 16 + arow_l) * ROWB + ks * 32 + aseg * 16);
                    LDSM_X4(a[mi][0], a[mi][1], a[mi][2], a[mi][3], sA + off);
                }
#pragma unroll
                for (int np = 0; np < 4; np++) {
                    uint32_t off = (uint32_t)((wn * 64 + np * 16 + brow_l) * ROWB + ks * 32 + bseg * 16);
                    LDSM_X4(bh[np*2][0], bh[np*2][1], bh[np*2+1][0], bh[np*2+1][1], sBh + off);
                    LDSM_X4(bl[np*2][0], bl[np*2][1], bl[np*2+1][0], bl[np*2+1][1], sBl + off);
                }
#pragma unroll
                for (int mi = 0; mi < 4; mi++)
#pragma unroll
                    for (int nt = 0; nt < 8; nt++) {
                        MMA_F16(acc[mi][nt], a[mi], bh[nt]);
                        MMA_F16(acc[mi][nt], a[mi], bl[nt]);
                    }
            }
            __syncthreads();
        }

        // epilogue
#pragma unroll
        for (int mi = 0; mi < 4; mi++) {
            int row = wm * 64 + mi * 16 + g;
#pragma unroll
            for (int nt = 0; nt < 8; nt++) {
                int col = wn * 64 + nt * 8 + tig * 2;
                *(float2*)&Cp[(ll)row * 1024 + col]       = make_float2(acc[mi][nt][0], acc[mi][nt][1]);
                *(float2*)&Cp[(ll)(row + 8) * 1024 + col] = make_float2(acc[mi][nt][2], acc[mi][nt][3]);
            }
        }
    }
}

// ============================ converters ============================
// fp32 -> fp16 (single), vectorized
__global__ __launch_bounds__(256) void convA_h_kernel(const float* __restrict__ x,
                                                      __half* __restrict__ y, int n4)
{
    int i = blockIdx.x * 256 + threadIdx.x;
    if (i >= n4) return;
    float4 v = *(const float4*)&x[(ll)i * 4];
    *(__half2*)&y[(ll)i * 4]     = __floats2half2_rn(v.x, v.y);
    *(__half2*)&y[(ll)i * 4 + 2] = __floats2half2_rn(v.z, v.w);
}

// weight transpose + fp16 hi/lo split, batched by blockIdx.z with stride wZ
__global__ __launch_bounds__(1024) void convWT_h_kernel(const float* __restrict__ W,
                                                        __half* __restrict__ hi,
                                                        __half* __restrict__ lo,
                                                        ll wZ)
{
    __shared__ float ts[32][33];
    const ll zo = (ll)blockIdx.z * wZ;
    int tx = threadIdx.x & 31, ty = threadIdx.x >> 5;
    int k0 = blockIdx.y * 32, n0 = blockIdx.x * 32;
    ts[ty][tx] = W[zo + (ll)(k0 + ty) * 1024 + n0 + tx];
    __syncthreads();
    float v = ts[tx][ty];   // = W[k0+tx][n0+ty]
    __half h = __float2half_rn(v);
    __half l = __float2half_rn(v - __half2float(h));
    hi[zo + (ll)(n0 + ty) * 1024 + k0 + tx] = h;
    lo[zo + (ll)(n0 + ty) * 1024 + k0 + tx] = l;
}

// ---------------- softmax over 128-wide head slices of Q -> fp16 ----------------
__global__ __launch_bounds__(256) void softmax128_h_kernel(const float* __restrict__ Q,
                                                           __half* __restrict__ out)
{
    ll row = ((ll)blockIdx.x << 3) + (threadIdx.x >> 5);
    int lane = threadIdx.x & 31;
    const float* p = Q + (row << 7);
    float4 v = *(const float4*)&p[lane << 2];
    float m = fmaxf(fmaxf(v.x, v.y), fmaxf(v.z, v.w));
#pragma unroll
    for (int o = 16; o > 0; o >>= 1) m = fmaxf(m, __shfl_xor_sync(0xffffffffu, m, o));
    float4 e;
    e.x = expf(v.x - m); e.y = expf(v.y - m);
    e.z = expf(v.z - m); e.w = expf(v.w - m);
    float s = e.x + e.y + e.z + e.w;
#pragma unroll
    for (int o = 16; o > 0; o >>= 1) s += __shfl_xor_sync(0xffffffffu, s, o);
    float inv = 1.f / s;
    ll o4 = (row << 7) + (lane << 2);
    *(__half2*)&out[o4]     = __floats2half2_rn(e.x * inv, e.y * inv);
    *(__half2*)&out[o4 + 2] = __floats2half2_rn(e.z * inv, e.w * inv);
}

// ---------------- fp32 tiled GEMM (small Z = Kvn @ Wout_h) ----------------
#define BM 128
#define BN 128
#define BK 16
__global__ __launch_bounds__(256) void sgemm_kernel(
    const float* __restrict__ A, const float* __restrict__ Bm, float* __restrict__ C,
    int K, int lda, int ldb, int ldc,
    ll aHi, ll aLo, ll bHi, ll bLo, ll cHi, ll cLo)
{
    const int z = blockIdx.z;
    A  += (ll)(z >> 3) * aHi + (ll)(z & 7) * aLo;
    Bm += (ll)(z >> 3) * bHi + (ll)(z & 7) * bLo;
    C  += (ll)(z >> 3) * cHi + (ll)(z & 7) * cLo;

    __shared__ float As[BK][BM];
    __shared__ float Bs[BK][BN];
    const int tid = threadIdx.x;
    const int ty = tid >> 4, tx = tid & 15;
    const int m0 = blockIdx.y * BM, n0 = blockIdx.x * BN;

    float acc[8][8];
#pragma unroll
    for (int i = 0; i < 8; i++)
#pragma unroll
        for (int j = 0; j < 8; j++) acc[i][j] = 0.f;

    for (int k0 = 0; k0 < K; k0 += BK) {
#pragma unroll
        for (int u = 0; u < 2; u++) {
            int idx = tid + u * 256;
            int r = idx >> 2, c4 = (idx & 3) << 2;
            float4 v = *(const float4*)&A[(ll)(m0 + r) * lda + k0 + c4];
            As[c4 + 0][r] = v.x; As[c4 + 1][r] = v.y;
            As[c4 + 2][r] = v.z; As[c4 + 3][r] = v.w;
        }
#pragma unroll
        for (int u = 0; u < 2; u++) {
            int idx = tid + u * 256;
            int r = idx >> 5, c4 = (idx & 31) << 2;
            *(float4*)&Bs[r][c4] = *(const float4*)&Bm[(ll)(k0 + r) * ldb + n0 + c4];
        }
        __syncthreads();
#pragma unroll
        for (int k = 0; k < BK; k++) {
            float4 a0 = *(const float4*)&As[k][ty * 8];
            float4 a1 = *(const float4*)&As[k][ty * 8 + 4];
            float4 b0 = *(const float4*)&Bs[k][tx * 8];
            float4 b1 = *(const float4*)&Bs[k][tx * 8 + 4];
            float a[8] = {a0.x,a0.y,a0.z,a0.w,a1.x,a1.y,a1.z,a1.w};
            float b[8] = {b0.x,b0.y,b0.z,b0.w,b1.x,b1.y,b1.z,b1.w};
#pragma unroll
            for (int i = 0; i < 8; i++)
#pragma unroll
                for (int j = 0; j < 8; j++) acc[i][j] += a[i] * b[j];
        }
        __syncthreads();
    }
#pragma unroll
    for (int i = 0; i < 8; i++) {
        int r = m0 + ty * 8 + i;
#pragma unroll
        for (int j = 0; j < 8; j += 4) {
            *(float4*)&C[(ll)r * ldc + n0 + tx * 8 + j] =
                make_float4(acc[i][j], acc[i][j+1], acc[i][j+2], acc[i][j+3]);
        }
    }
}

// ---------------- Kv partial over 256-token chunks (fp32) ----------------
__global__ __launch_bounds__(256) void kv_partial_kernel(void)
{
    const int z  = blockIdx.x;
    const int tc = blockIdx.y;
    const int b = z >> 3, h = z & 7;
    const float* Ab = g_K + (ll)b * TT * LATD + h * DHD;
    const float* Bb = g_V + (ll)b * TT * DD   + h * DHD;

    __shared__ float As[16][128];
    __shared__ float Bs[16][128];
    const int tid = threadIdx.x;
    const int ty = tid >> 4, tx = tid & 15;
    float acc[8][8];
#pragma unroll
    for (int i = 0; i < 8; i++)
#pragma unroll
        for (int j = 0; j < 8; j++) acc[i][j] = 0.f;
    float ksum = 0.f;

    const int t0 = tc * TCHUNK;
    for (int tt = 0; tt < TCHUNK; tt += 16) {
#pragma unroll
        for (int u = 0; u < 2; u++) {
            int idx = tid + u * 256;
            int k = idx >> 5, i4 = (idx & 31) << 2;
            ll trow = (ll)(t0 + tt + k);
            float4 va = *(const float4*)&Ab[trow * LATD + i4];
            As[k][i4 + 0] = expf(va.x); As[k][i4 + 1] = expf(va.y);
            As[k][i4 + 2] = expf(va.z); As[k][i4 + 3] = expf(va.w);
            *(float4*)&Bs[k][i4] = *(const float4*)&Bb[trow * DD + i4];
        }
        __syncthreads();
        if (tid < 128) {
#pragma unroll
            for (int k = 0; k < 16; k++) ksum += As[k][tid];
        }
#pragma unroll
        for (int k = 0; k < 16; k++) {
            float4 a0 = *(const float4*)&As[k][ty * 8];
            float4 a1 = *(const float4*)&As[k][ty * 8 + 4];
            float4 b0 = *(const float4*)&Bs[k][tx * 8];
            float4 b1 = *(const float4*)&Bs[k][tx * 8 + 4];
            float a[8] = {a0.x,a0.y,a0.z,a0.w,a1.x,a1.y,a1.z,a1.w};
            float b[8] = {b0.x,b0.y,b0.z,b0.w,b1.x,b1.y,b1.z,b1.w};
#pragma unroll
            for (int i = 0; i < 8; i++)
#pragma unroll
                for (int j = 0; j < 8; j++) acc[i][j] += a[i] * b[j];
        }
        __syncthreads();
    }

    float* Cp = g_Kvpart + ((ll)tc * 32 + z) * (128 * 128);
#pragma unroll
    for (int i = 0; i < 8; i++) {
        int r = ty * 8 + i;
#pragma unroll
        for (int j = 0; j < 8; j += 4) {
            *(float4*)&Cp[r * 128 + tx * 8 + j] =
                make_float4(acc[i][j], acc[i][j+1], acc[i][j+2], acc[i][j+3]);
        }
    }
    if (tid < 128) g_Ksumpart[((ll)tc * 32 + z) * 128 + tid] = ksum;
}

__global__ __launch_bounds__(128) void kv_reduce_norm_kernel(void)
{
    const int j  = threadIdx.x;
    const int zi = blockIdx.x;
    const int z = zi >> 7, i = zi & 127;
    float kv = 0.f, s = 0.f;
#pragma unroll
    for (int tc = 0; tc < TSPLIT; tc++) {
        kv += g_Kvpart[((ll)tc * 32 + z) * 16384 + i * 128 + j];
        s  += g_Ksumpart[((ll)tc * 32 + z) * 128 + i];
    }
    g_Kvn[(ll)z * 16384 + i * 128 + j] = kv / s;
}

// ---------------- launch ----------------
extern "C" void kernel_launch(void* const* d_in, const int* in_sizes, int n_in,
                              void* d_out, int out_size)
{
    const float* query = (const float*)d_in[0];
    const float* key   = (const float*)d_in[1];
    const float* wq    = (const float*)d_in[2];
    const float* wk    = (const float*)d_in[3];
    const float* wv    = (const float*)d_in[4];
    const float* wproj = (const float*)d_in[5];
    float* out = (float*)d_out;

    float *Q, *K, *V, *Z, *Kvn;
    __half *Aq, *Ak, *Bh, *Bl;
    cudaGetSymbolAddress((void**)&Q,   g_Q);
    cudaGetSymbolAddress((void**)&K,   g_K);
    cudaGetSymbolAddress((void**)&V,   g_V);
    cudaGetSymbolAddress((void**)&Z,   g_Z);
    cudaGetSymbolAddress((void**)&Kvn, g_Kvn);
    cudaGetSymbolAddress((void**)&Aq,  g_Aq);
    cudaGetSymbolAddress((void**)&Ak,  g_Ak);
    cudaGetSymbolAddress((void**)&Bh,  g_Bh);
    cudaGetSymbolAddress((void**)&Bl,  g_Bl);

    cudaFuncSetAttribute(phmma_kernel, cudaFuncAttributeMaxDynamicSharedMemorySize, GEMM_SMEM);

    int nsm = 148;
    cudaDeviceGetAttribute(&nsm, cudaDevAttrMultiProcessorCount, 0);
    const int pgrid = nsm * 2;

    const int MBT = BATCH * TT;                 // 16384
    const int actN4 = MBT * DD / 4;
    dim3 gconvA((actN4 + 255) / 256), bconvA(256);
    dim3 gconvW(32, 32, 1), bconvW(1024);

    // ---- converts: activations single fp16, weights transposed hi/lo fp16 ----
    convA_h_kernel<<<gconvA, bconvA>>>(query, Aq, actN4);
    convA_h_kernel<<<gconvA, bconvA>>>(key,   Ak, actN4);
    convWT_h_kernel<<<gconvW, bconvW>>>(wq, Bh + 0ll * 1048576, Bl + 0ll * 1048576, 0);
    convWT_h_kernel<<<gconvW, bconvW>>>(wk, Bh + 1ll * 1048576, Bl + 1ll * 1048576, 0);
    convWT_h_kernel<<<gconvW, bconvW>>>(wv, Bh + 2ll * 1048576, Bl + 2ll * 1048576, 0);

    // ---- persistent QKV mega-GEMM (3 x 1024 tiles) ----
    GemmJobs jq;
    jq.A[0] = Aq;  jq.A[1] = Ak;  jq.A[2] = Ak;
    jq.Bh[0] = Bh; jq.Bh[1] = Bh + 1048576; jq.Bh[2] = Bh + 2097152;
    jq.Bl[0] = Bl; jq.Bl[1] = Bl + 1048576; jq.Bl[2] = Bl + 2097152;
    jq.C[0] = Q;   jq.C[1] = K;   jq.C[2] = V;
    jq.total = 3072; jq.bShift = -1; jq.bStride = 0;
    phmma_kernel<<<pgrid, 128, GEMM_SMEM>>>(jq);

    // ---- softmax(Q) -> fp16 into Aq (query operand no longer needed) ----
    softmax128_h_kernel<<<(MBT * NH) / 8, 256>>>(Q, Aq);

    // ---- Kv aggregation + normalize -> Kvn ----
    kv_partial_kernel<<<dim3(32, TSPLIT, 1), 256>>>();
    kv_reduce_norm_kernel<<<dim3(32 * 128, 1, 1), 128>>>();

    // ---- Z[b, h*128+l, n] = sum_d Kvn[b,h,l,d] * Wout[h*128+d, n] ----
    dim3 gz(8, 1, 32);
    sgemm_kernel<<<gz, 256>>>(Kvn, wproj, Z, 128, 128, 1024, 1024,
                              (ll)8 * 16384, 16384,
                              0, 131072,
                              1048576, 131072);

    // ---- convert Z (4 batches) -> Bh/Bl, then persistent OUT GEMM ----
    dim3 gconvWZ(32, 32, 4);
    convWT_h_kernel<<<gconvWZ, bconvW>>>(Z, Bh, Bl, 1048576);

    GemmJobs jo;
    jo.A[0] = Aq;  jo.A[1] = Aq;  jo.A[2] = Aq;
    jo.Bh[0] = Bh; jo.Bh[1] = Bh; jo.Bh[2] = Bh;
    jo.Bl[0] = Bl; jo.Bl[1] = Bl; jo.Bl[2] = Bl;
    jo.C[0] = out; jo.C[1] = out; jo.C[2] = out;
    jo.total = 1024; jo.bShift = 5; jo.bStride = 1048576;   // b = m_idx>>5 (32 m-tiles/batch)
    phmma_kernel<<<pgrid, 128, GEMM_SMEM>>>(jo);
}

// round 8
// speedup vs baseline: 1.4078x; 1.0175x over previous
#include <cuda_runtime.h>
#include <cuda_fp16.h>
#include <math.h>
#include <stdint.h>

// Problem constants
#define BATCH 4
#define TT    4096
#define DD    1024
#define LATD  1024
#define NH    8
#define DHD   128
#define TSPLIT 16
#define TCHUNK (TT / TSPLIT)   // 256

typedef long long ll;

// ---------------- scratch (device globals; no allocation allowed) ----------------
__device__ float g_Q[(size_t)BATCH * TT * LATD];
__device__ float g_K[(size_t)BATCH * TT * LATD];
__device__ float g_V[(size_t)BATCH * TT * DD];
__device__ float g_Z[(size_t)BATCH * DD * DD];
__device__ float g_Kvpart[(size_t)TSPLIT * 32 * 128 * 128];
__device__ float g_Ksumpart[(size_t)TSPLIT * 32 * 128];
__device__ float g_Kvn[(size_t)32 * 128 * 128];
// fp16 operand buffers
__device__ __half g_Aq[(size_t)BATCH * TT * DD];   // query fp16, later softmax(Q) fp16
__device__ __half g_Ak[(size_t)BATCH * TT * DD];   // key fp16
__device__ __half g_Bh[(size_t)4 * DD * DD];       // weight^T hi: slots wq,wk,wv | Z(4 batches)
__device__ __half g_Bl[(size_t)4 * DD * DD];       // weight^T lo

// ============================ PTX helpers ============================
__device__ __forceinline__ uint32_t smem_u32(const void* p) {
    uint32_t a;
    asm("{ .reg .u64 t; cvta.to.shared.u64 t, %1; cvt.u32.u64 %0, t; }" : "=r"(a) : "l"(p));
    return a;
}
#define CP_ASYNC16(s, g) asm volatile("cp.async.cg.shared.global [%0], [%1], 16;" :: "r"(s), "l"(g))
#define CP_COMMIT() asm volatile("cp.async.commit_group;" ::: "memory")
#define CP_WAIT(n)  asm volatile("cp.async.wait_group %0;" :: "n"(n) : "memory")

#define LDSM_X4(r0, r1, r2, r3, a) \
    asm volatile("ldmatrix.sync.aligned.m8n8.x4.shared.b16 {%0,%1,%2,%3}, [%4];" \
                 : "=r"(r0), "=r"(r1), "=r"(r2), "=r"(r3) : "r"(a))

#define MMA_F16(c, a, b) \
    asm volatile("mma.sync.aligned.m16n8k16.row.col.f32.f16.f16.f32 " \
                 "{%0,%1,%2,%3}, {%4,%5,%6,%7}, {%8,%9}, {%0,%1,%2,%3};" \
                 : "+f"((c)[0]), "+f"((c)[1]), "+f"((c)[2]), "+f"((c)[3]) \
                 : "r"((a)[0]), "r"((a)[1]), "r"((a)[2]), "r"((a)[3]), \
                   "r"((b)[0]), "r"((b)[1]))

// ============================ persistent 2-term fp16 HMMA GEMM ============================
// C_tile[128,128] = A[128rows,K=1024] x (Bh+Bl)[128rows,K=1024]^T   (B N-major "col")
// Tile 128x128, 4 warps (64x64 each), K-chunk 64, 2-stage cp.async, 2 CTAs/SM.
// Inner loop: full bh sweep then full bl sweep -> 32-instruction dependency
// distance per accumulator (no back-to-back RAW HMMA stalls).
#define NKC 16
#define ROWB 144                 // 128B data + 16B pad
#define SUBT (128 * ROWB)        // 18432
#define STAGEB (3 * SUBT)        // A, Bh, Bl = 55296
#define GEMM_SMEM (2 * STAGEB)   // 110592

struct GemmJobs {
    const __half* A[3];
    const __half* Bh[3];
    const __half* Bl[3];
    float*        C[3];
    int total;       // total tiles (njobs * 1024)
    int bShift;      // -1, or m_idx>>bShift selects B batch
    ll  bStride;     // element stride between B batches
};

__global__ __launch_bounds__(128, 2) void phmma_kernel(GemmJobs J)
{
    extern __shared__ char dsm[];
    const uint32_t sbase = smem_u32(dsm);
    const int tid = threadIdx.x;
    const int wid = tid >> 5, lane = tid & 31;
    const int wm = wid & 1, wn = wid >> 1;
    const int arow_l = lane & 15, aseg = lane >> 4;
    const int brow_l = (lane & 7) + ((lane >> 4) << 3), bseg = (lane >> 3) & 1;
    const int g = lane >> 2, tig = lane & 3;

    for (int t = blockIdx.x; t < J.total; t += gridDim.x) {
        const int job = t >> 10;            // 1024 tiles per job
        const int rem = t & 1023;
        const int mI = rem >> 3, nI = rem & 7;

        const __half* Ap  = J.A[job]  + (ll)mI * 131072;
        const __half* Bhp = J.Bh[job];
        const __half* Blp = J.Bl[job];
        if (J.bShift >= 0) {
            ll bo = (ll)(mI >> J.bShift) * J.bStride;
            Bhp += bo; Blp += bo;
        }
        Bhp += (ll)nI * 131072;
        Blp += (ll)nI * 131072;
        float* Cp = J.C[job] + (ll)mI * 131072 + nI * 128;

        float acc[4][8][4];
#pragma unroll
        for (int i = 0; i < 4; i++)
#pragma unroll
            for (int j = 0; j < 8; j++)
#pragma unroll
                for (int v = 0; v < 4; v++) acc[i][j][v] = 0.f;

        // ---- stage loader: A, Bh, Bl each 128 rows x 128B ----
        auto load_stage = [&](int s, int kc) {
            uint32_t st = sbase + s * STAGEB;
            const int k0 = kc * 64;
            const __half* gs[3] = { Ap + k0, Bhp + k0, Blp + k0 };
#pragma unroll
            for (int sub = 0; sub < 3; sub++) {
                const __half* gg = gs[sub];
                uint32_t base = st + sub * SUBT;
#pragma unroll
                for (int u = 0; u < 8; u++) {
                    int idx = tid + u * 128;      // 0..1023
                    int r = idx >> 3, ch = idx & 7;
                    CP_ASYNC16(base + r * ROWB + ch * 16, gg + (ll)r * 1024 + ch * 8);
                }
            }
            CP_COMMIT();
        };

        load_stage(0, 0);
        for (int kc = 0; kc < NKC; kc++) {
            const int s = kc & 1;
            if (kc + 1 < NKC) { load_stage(s ^ 1, kc + 1); CP_WAIT(1); }
            else               CP_WAIT(0);
            __syncthreads();

            const uint32_t st = sbase + s * STAGEB;
            const uint32_t sA = st, sBh = st + SUBT, sBl = st + 2 * SUBT;

#pragma unroll
            for (int ks = 0; ks < 4; ks++) {
                uint32_t a[4][4], bh[8][2], bl[8][2];
#pragma unroll
                for (int mi = 0; mi < 4; mi++) {
                    uint32_t off = (uint32_t)((wm * 64 + mi * 16 + arow_l) * ROWB + ks * 32 + aseg * 16);
                    LDSM_X4(a[mi][0], a[mi][1], a[mi][2], a[mi][3], sA + off);
                }
#pragma unroll
                for (int np = 0; np < 4; np++) {
                    uint32_t off = (uint32_t)((wn * 64 + np * 16 + brow_l) * ROWB + ks * 32 + bseg * 16);
                    LDSM_X4(bh[np*2][0], bh[np*2][1], bh[np*2+1][0], bh[np*2+1][1], sBh + off);
                    LDSM_X4(bl[np*2][0], bl[np*2][1], bl[np*2+1][0], bl[np*2+1][1], sBl + off);
                }
                // full bh sweep (each accumulator touched once) ...
#pragma unroll
                for (int mi = 0; mi < 4; mi++)
#pragma unroll
                    for (int nt = 0; nt < 8; nt++)
                        MMA_F16(acc[mi][nt], a[mi], bh[nt]);
                // ... then full bl sweep: RAW distance = 32 MMAs per accumulator
#pragma unroll
                for (int mi = 0; mi < 4; mi++)
#pragma unroll
                    for (int nt = 0; nt < 8; nt++)
                        MMA_F16(acc[mi][nt], a[mi], bl[nt]);
            }
            __syncthreads();
        }

        // epilogue
#pragma unroll
        for (int mi = 0; mi < 4; mi++) {
            int row = wm * 64 + mi * 16 + g;
#pragma unroll
            for (int nt = 0; nt < 8; nt++) {
                int col = wn * 64 + nt * 8 + tig * 2;
                *(float2*)&Cp[(ll)row * 1024 + col]       = make_float2(acc[mi][nt][0], acc[mi][nt][1]);
                *(float2*)&Cp[(ll)(row + 8) * 1024 + col] = make_float2(acc[mi][nt][2], acc[mi][nt][3]);
            }
        }
    }
}

// ============================ converters ============================
// fp32 -> fp16 (single), vectorized
__global__ __launch_bounds__(256) void convA_h_kernel(const float* __restrict__ x,
                                                      __half* __restrict__ y, int n4)
{
    int i = blockIdx.x * 256 + threadIdx.x;
    if (i >= n4) return;
    float4 v = *(const float4*)&x[(ll)i * 4];
    *(__half2*)&y[(ll)i * 4]     = __floats2half2_rn(v.x, v.y);
    *(__half2*)&y[(ll)i * 4 + 2] = __floats2half2_rn(v.z, v.w);
}

// weight transpose + fp16 hi/lo split, batched by blockIdx.z with stride wZ
__global__ __launch_bounds__(1024) void convWT_h_kernel(const float* __restrict__ W,
                                                        __half* __restrict__ hi,
                                                        __half* __restrict__ lo,
                                                        ll wZ)
{
    __shared__ float ts[32][33];
    const ll zo = (ll)blockIdx.z * wZ;
    int tx = threadIdx.x & 31, ty = threadIdx.x >> 5;
    int k0 = blockIdx.y * 32, n0 = blockIdx.x * 32;
    ts[ty][tx] = W[zo + (ll)(k0 + ty) * 1024 + n0 + tx];
    __syncthreads();
    float v = ts[tx][ty];   // = W[k0+tx][n0+ty]
    __half h = __float2half_rn(v);
    __half l = __float2half_rn(v - __half2float(h));
    hi[zo + (ll)(n0 + ty) * 1024 + k0 + tx] = h;
    lo[zo + (ll)(n0 + ty) * 1024 + k0 + tx] = l;
}

// ---------------- softmax over 128-wide head slices of Q -> fp16 ----------------
__global__ __launch_bounds__(256) void softmax128_h_kernel(const float* __restrict__ Q,
                                                           __half* __restrict__ out)
{
    ll row = ((ll)blockIdx.x << 3) + (threadIdx.x >> 5);
    int lane = threadIdx.x & 31;
    const float* p = Q + (row << 7);
    float4 v = *(const float4*)&p[lane << 2];
    float m = fmaxf(fmaxf(v.x, v.y), fmaxf(v.z, v.w));
#pragma unroll
    for (int o = 16; o > 0; o >>= 1) m = fmaxf(m, __shfl_xor_sync(0xffffffffu, m, o));
    float4 e;
    e.x = expf(v.x - m); e.y = expf(v.y - m);
    e.z = expf(v.z - m); e.w = expf(v.w - m);
    float s = e.x + e.y + e.z + e.w;
#pragma unroll
    for (int o = 16; o > 0; o >>= 1) s += __shfl_xor_sync(0xffffffffu, s, o);
    float inv = 1.f / s;
    ll o4 = (row << 7) + (lane << 2);
    *(__half2*)&out[o4]     = __floats2half2_rn(e.x * inv, e.y * inv);
    *(__half2*)&out[o4 + 2] = __floats2half2_rn(e.z * inv, e.w * inv);
}

// ---------------- fp32 tiled GEMM (small Z = Kvn @ Wout_h) ----------------
#define BM 128
#define BN 128
#define BK 16
__global__ __launch_bounds__(256) void sgemm_kernel(
    const float* __restrict__ A, const float* __restrict__ Bm, float* __restrict__ C,
    int K, int lda, int ldb, int ldc,
    ll aHi, ll aLo, ll bHi, ll bLo, ll cHi, ll cLo)
{
    const int z = blockIdx.z;
    A  += (ll)(z >> 3) * aHi + (ll)(z & 7) * aLo;
    Bm += (ll)(z >> 3) * bHi + (ll)(z & 7) * bLo;
    C  += (ll)(z >> 3) * cHi + (ll)(z & 7) * cLo;

    __shared__ float As[BK][BM];
    __shared__ float Bs[BK][BN];
    const int tid = threadIdx.x;
    const int ty = tid >> 4, tx = tid & 15;
    const int m0 = blockIdx.y * BM, n0 = blockIdx.x * BN;

    float acc[8][8];
#pragma unroll
    for (int i = 0; i < 8; i++)
#pragma unroll
        for (int j = 0; j < 8; j++) acc[i][j] = 0.f;

    for (int k0 = 0; k0 < K; k0 += BK) {
#pragma unroll
        for (int u = 0; u < 2; u++) {
            int idx = tid + u * 256;
            int r = idx >> 2, c4 = (idx & 3) << 2;
            float4 v = *(const float4*)&A[(ll)(m0 + r) * lda + k0 + c4];
            As[c4 + 0][r] = v.x; As[c4 + 1][r] = v.y;
            As[c4 + 2][r] = v.z; As[c4 + 3][r] = v.w;
        }
#pragma unroll
        for (int u = 0; u < 2; u++) {
            int idx = tid + u * 256;
            int r = idx >> 5, c4 = (idx & 31) << 2;
            *(float4*)&Bs[r][c4] = *(const float4*)&Bm[(ll)(k0 + r) * ldb + n0 + c4];
        }
        __syncthreads();
#pragma unroll
        for (int k = 0; k < BK; k++) {
            float4 a0 = *(const float4*)&As[k][ty * 8];
            float4 a1 = *(const float4*)&As[k][ty * 8 + 4];
            float4 b0 = *(const float4*)&Bs[k][tx * 8];
            float4 b1 = *(const float4*)&Bs[k][tx * 8 + 4];
            float a[8] = {a0.x,a0.y,a0.z,a0.w,a1.x,a1.y,a1.z,a1.w};
            float b[8] = {b0.x,b0.y,b0.z,b0.w,b1.x,b1.y,b1.z,b1.w};
#pragma unroll
            for (int i = 0; i < 8; i++)
#pragma unroll
                for (int j = 0; j < 8; j++) acc[i][j] += a[i] * b[j];
        }
        __syncthreads();
    }
#pragma unroll
    for (int i = 0; i < 8; i++) {
        int r = m0 + ty * 8 + i;
#pragma unroll
        for (int j = 0; j < 8; j += 4) {
            *(float4*)&C[(ll)r * ldc + n0 + tx * 8 + j] =
                make_float4(acc[i][j], acc[i][j+1], acc[i][j+2], acc[i][j+3]);
        }
    }
}

// ---------------- Kv partial over 256-token chunks (fp32) ----------------
__global__ __launch_bounds__(256) void kv_partial_kernel(void)
{
    const int z  = blockIdx.x;
    const int tc = blockIdx.y;
    const int b = z >> 3, h = z & 7;
    const float* Ab = g_K + (ll)b * TT * LATD + h * DHD;
    const float* Bb = g_V + (ll)b * TT * DD   + h * DHD;

    __shared__ float As[16][128];
    __shared__ float Bs[16][128];
    const int tid = threadIdx.x;
    const int ty = tid >> 4, tx = tid & 15;
    float acc[8][8];
#pragma unroll
    for (int i = 0; i < 8; i++)
#pragma unroll
        for (int j = 0; j < 8; j++) acc[i][j] = 0.f;
    float ksum = 0.f;

    const int t0 = tc * TCHUNK;
    for (int tt = 0; tt < TCHUNK; tt += 16) {
#pragma unroll
        for (int u = 0; u < 2; u++) {
            int idx = tid + u * 256;
            int k = idx >> 5, i4 = (idx & 31) << 2;
            ll trow = (ll)(t0 + tt + k);
            float4 va = *(const float4*)&Ab[trow * LATD + i4];
            As[k][i4 + 0] = expf(va.x); As[k][i4 + 1] = expf(va.y);
            As[k][i4 + 2] = expf(va.z); As[k][i4 + 3] = expf(va.w);
            *(float4*)&Bs[k][i4] = *(const float4*)&Bb[trow * DD + i4];
        }
        __syncthreads();
        if (tid < 128) {
#pragma unroll
            for (int k = 0; k < 16; k++) ksum += As[k][tid];
        }
#pragma unroll
        for (int k = 0; k < 16; k++) {
            float4 a0 = *(const float4*)&As[k][ty * 8];
            float4 a1 = *(const float4*)&As[k][ty * 8 + 4];
            float4 b0 = *(const float4*)&Bs[k][tx * 8];
            float4 b1 = *(const float4*)&Bs[k][tx * 8 + 4];
            float a[8] = {a0.x,a0.y,a0.z,a0.w,a1.x,a1.y,a1.z,a1.w};
            float b[8] = {b0.x,b0.y,b0.z,b0.w,b1.x,b1.y,b1.z,b1.w};
#pragma unroll
            for (int i = 0; i < 8; i++)
#pragma unroll
                for (int j = 0; j < 8; j++) acc[i][j] += a[i] * b[j];
        }
        __syncthreads();
    }

    float* Cp = g_Kvpart + ((ll)tc * 32 + z) * (128 * 128);
#pragma unroll
    for (int i = 0; i < 8; i++) {
        int r = ty * 8 + i;
#pragma unroll
        for (int j = 0; j < 8; j += 4) {
            *(float4*)&Cp[r * 128 + tx * 8 + j] =
                make_float4(acc[i][j], acc[i][j+1], acc[i][j+2], acc[i][j+3]);
        }
    }
    if (tid < 128) g_Ksumpart[((ll)tc * 32 + z) * 128 + tid] = ksum;
}

__global__ __launch_bounds__(128) void kv_reduce_norm_kernel(void)
{
    const int j  = threadIdx.x;
    const int zi = blockIdx.x;
    const int z = zi >> 7, i = zi & 127;
    float kv = 0.f, s = 0.f;
#pragma unroll
    for (int tc = 0; tc < TSPLIT; tc++) {
        kv += g_Kvpart[((ll)tc * 32 + z) * 16384 + i * 128 + j];
        s  += g_Ksumpart[((ll)tc * 32 + z) * 128 + i];
    }
    g_Kvn[(ll)z * 16384 + i * 128 + j] = kv / s;
}

// ---------------- launch ----------------
extern "C" void kernel_launch(void* const* d_in, const int* in_sizes, int n_in,
                              void* d_out, int out_size)
{
    const float* query = (const float*)d_in[0];
    const float* key   = (const float*)d_in[1];
    const float* wq    = (const float*)d_in[2];
    const float* wk    = (const float*)d_in[3];
    const float* wv    = (const float*)d_in[4];
    const float* wproj = (const float*)d_in[5];
    float* out = (float*)d_out;

    float *Q, *K, *V, *Z, *Kvn;
    __half *Aq, *Ak, *Bh, *Bl;
    cudaGetSymbolAddress((void**)&Q,   g_Q);
    cudaGetSymbolAddress((void**)&K,   g_K);
    cudaGetSymbolAddress((void**)&V,   g_V);
    cudaGetSymbolAddress((void**)&Z,   g_Z);
    cudaGetSymbolAddress((void**)&Kvn, g_Kvn);
    cudaGetSymbolAddress((void**)&Aq,  g_Aq);
    cudaGetSymbolAddress((void**)&Ak,  g_Ak);
    cudaGetSymbolAddress((void**)&Bh,  g_Bh);
    cudaGetSymbolAddress((void**)&Bl,  g_Bl);

    cudaFuncSetAttribute(phmma_kernel, cudaFuncAttributeMaxDynamicSharedMemorySize, GEMM_SMEM);

    int nsm = 148;
    cudaDeviceGetAttribute(&nsm, cudaDevAttrMultiProcessorCount, 0);
    const int pgrid = nsm * 2;

    const int MBT = BATCH * TT;                 // 16384
    const int actN4 = MBT * DD / 4;
    dim3 gconvA((actN4 + 255) / 256), bconvA(256);
    dim3 gconvW(32, 32, 1), bconvW(1024);

    // ---- converts: activations single fp16, weights transposed hi/lo fp16 ----
    convA_h_kernel<<<gconvA, bconvA>>>(query, Aq, actN4);
    convA_h_kernel<<<gconvA, bconvA>>>(key,   Ak, actN4);
    convWT_h_kernel<<<gconvW, bconvW>>>(wq, Bh + 0ll * 1048576, Bl + 0ll * 1048576, 0);
    convWT_h_kernel<<<gconvW, bconvW>>>(wk, Bh + 1ll * 1048576, Bl + 1ll * 1048576, 0);
    convWT_h_kernel<<<gconvW, bconvW>>>(wv, Bh + 2ll * 1048576, Bl + 2ll * 1048576, 0);

    // ---- persistent QKV mega-GEMM (3 x 1024 tiles) ----
    GemmJobs jq;
    jq.A[0] = Aq;  jq.A[1] = Ak;  jq.A[2] = Ak;
    jq.Bh[0] = Bh; jq.Bh[1] = Bh + 1048576; jq.Bh[2] = Bh + 2097152;
    jq.Bl[0] = Bl; jq.Bl[1] = Bl + 1048576; jq.Bl[2] = Bl + 2097152;
    jq.C[0] = Q;   jq.C[1] = K;   jq.C[2] = V;
    jq.total = 3072; jq.bShift = -1; jq.bStride = 0;
    phmma_kernel<<<pgrid, 128, GEMM_SMEM>>>(jq);

    // ---- softmax(Q) -> fp16 into Aq ----
    softmax128_h_kernel<<<(MBT * NH) / 8, 256>>>(Q, Aq);

    // ---- Kv aggregation + normalize -> Kvn ----
    kv_partial_kernel<<<dim3(32, TSPLIT, 1), 256>>>();
    kv_reduce_norm_kernel<<<dim3(32 * 128, 1, 1), 128>>>();

    // ---- Z[b, h*128+l, n] = sum_d Kvn[b,h,l,d] * Wout[h*128+d, n] ----
    dim3 gz(8, 1, 32);
    sgemm_kernel<<<gz, 256>>>(Kvn, wproj, Z, 128, 128, 1024, 1024,
                              (ll)8 * 16384, 16384,
                              0, 131072,
                              1048576, 131072);

    // ---- convert Z (4 batches) -> Bh/Bl, then persistent OUT GEMM ----
    dim3 gconvWZ(32, 32, 4);
    convWT_h_kernel<<<gconvWZ, bconvW>>>(Z, Bh, Bl, 1048576);

    GemmJobs jo;
    jo.A[0] = Aq;  jo.A[1] = Aq;  jo.A[2] = Aq;
    jo.Bh[0] = Bh; jo.Bh[1] = Bh; jo.Bh[2] = Bh;
    jo.Bl[0] = Bl; jo.Bl[1] = Bl; jo.Bl[2] = Bl;
    jo.C[0] = out; jo.C[1] = out; jo.C[2] = out;
    jo.total = 1024; jo.bShift = 5; jo.bStride = 1048576;   // b = m_idx>>5
    phmma_kernel<<<pgrid, 128, GEMM_SMEM>>>(jo);
}

// round 9
// speedup vs baseline: 2.0540x; 1.4591x over previous
#include <cuda_runtime.h>
#include <cuda_fp16.h>
#include <math.h>
#include <stdint.h>

// Problem constants
#define BATCH 4
#define TT    4096
#define DD    1024
#define LATD  1024
#define NH    8
#define DHD   128
#define TSPLIT 16
#define TCHUNK (TT / TSPLIT)   // 256

typedef long long ll;

// ---------------- scratch (device globals; no allocation allowed) ----------------
__device__ float g_Q[(size_t)BATCH * TT * LATD];
__device__ float g_K[(size_t)BATCH * TT * LATD];
__device__ float g_V[(size_t)BATCH * TT * DD];
__device__ float g_Z[(size_t)BATCH * DD * DD];
__device__ float g_Kvpart[(size_t)TSPLIT * 32 * 128 * 128];
__device__ float g_Ksumpart[(size_t)TSPLIT * 32 * 128];
__device__ float g_Kvn[(size_t)32 * 128 * 128];
// fp16 operand buffers
__device__ __half g_Aq[(size_t)BATCH * TT * DD];   // query fp16, later softmax(Q) fp16
__device__ __half g_Ak[(size_t)BATCH * TT * DD];   // key fp16
__device__ __half g_Bw[(size_t)4 * DD * DD];       // weight^T fp16: slots wq,wk,wv | Z(4 batches)

// ============================ PTX helpers ============================
__device__ __forceinline__ uint32_t smem_u32(const void* p) {
    uint32_t a;
    asm("{ .reg .u64 t; cvta.to.shared.u64 t, %1; cvt.u32.u64 %0, t; }" : "=r"(a) : "l"(p));
    return a;
}
#define CP_ASYNC16(s, g) asm volatile("cp.async.cg.shared.global [%0], [%1], 16;" :: "r"(s), "l"(g))
#define CP_COMMIT() asm volatile("cp.async.commit_group;" ::: "memory")
#define CP_WAIT(n)  asm volatile("cp.async.wait_group %0;" :: "n"(n) : "memory")

#define LDSM_X4(r0, r1, r2, r3, a) \
    asm volatile("ldmatrix.sync.aligned.m8n8.x4.shared.b16 {%0,%1,%2,%3}, [%4];" \
                 : "=r"(r0), "=r"(r1), "=r"(r2), "=r"(r3) : "r"(a))

#define MMA_F16(c, a, b) \
    asm volatile("mma.sync.aligned.m16n8k16.row.col.f32.f16.f16.f32 " \
                 "{%0,%1,%2,%3}, {%4,%5,%6,%7}, {%8,%9}, {%0,%1,%2,%3};" \
                 : "+f"((c)[0]), "+f"((c)[1]), "+f"((c)[2]), "+f"((c)[3]) \
                 : "r"((a)[0]), "r"((a)[1]), "r"((a)[2]), "r"((a)[3]), \
                   "r"((b)[0]), "r"((b)[1]))

// ============================ persistent single-fp16 HMMA GEMM ============================
// C_tile[128,128] = A[128rows,K=1024] x B[128rows,K=1024]^T   (B N-major "col")
// Tile 128x128, 4 warps (64x64 each), K-chunk 64, 3-stage cp.async, 2 CTAs/SM.
#define NKC 16
#define ROWB 144                 // 128B data + 16B pad
#define SUBT (128 * ROWB)        // 18432
#define STAGEB (2 * SUBT)        // A, B = 36864
#define NSTG 3
#define GEMM_SMEM (NSTG * STAGEB)   // 110592

struct GemmJobs {
    const __half* A[3];
    const __half* B[3];
    float*        C[3];
    int total;       // total tiles (njobs * 1024)
    int bShift;      // -1, or m_idx>>bShift selects B batch
    ll  bStride;     // element stride between B batches
};

__global__ __launch_bounds__(128, 2) void phmma_kernel(GemmJobs J)
{
    extern __shared__ char dsm[];
    const uint32_t sbase = smem_u32(dsm);
    const int tid = threadIdx.x;
    const int wid = tid >> 5, lane = tid & 31;
    const int wm = wid & 1, wn = wid >> 1;
    const int arow_l = lane & 15, aseg = lane >> 4;
    const int brow_l = (lane & 7) + ((lane >> 4) << 3), bseg = (lane >> 3) & 1;
    const int g = lane >> 2, tig = lane & 3;

    for (int t = blockIdx.x; t < J.total; t += gridDim.x) {
        const int job = t >> 10;            // 1024 tiles per job
        const int rem = t & 1023;
        const int mI = rem >> 3, nI = rem & 7;

        const __half* Ap = J.A[job] + (ll)mI * 131072;
        const __half* Bp = J.B[job];
        if (J.bShift >= 0) Bp += (ll)(mI >> J.bShift) * J.bStride;
        Bp += (ll)nI * 131072;
        float* Cp = J.C[job] + (ll)mI * 131072 + nI * 128;

        float acc[4][8][4];
#pragma unroll
        for (int i = 0; i < 4; i++)
#pragma unroll
            for (int j = 0; j < 8; j++)
#pragma unroll
                for (int v = 0; v < 4; v++) acc[i][j][v] = 0.f;

        // ---- stage loader: A, B each 128 rows x 128B ----
        auto load_stage = [&](int s, int kc) {
            uint32_t st = sbase + s * STAGEB;
            const int k0 = kc * 64;
            const __half* gs[2] = { Ap + k0, Bp + k0 };
#pragma unroll
            for (int sub = 0; sub < 2; sub++) {
                const __half* gg = gs[sub];
                uint32_t base = st + sub * SUBT;
#pragma unroll
                for (int u = 0; u < 8; u++) {
                    int idx = tid + u * 128;      // 0..1023
                    int r = idx >> 3, ch = idx & 7;
                    CP_ASYNC16(base + r * ROWB + ch * 16, gg + (ll)r * 1024 + ch * 8);
                }
            }
            CP_COMMIT();
        };

        load_stage(0, 0);
        load_stage(1, 1);
        for (int kc = 0; kc < NKC; kc++) {
            const int s = kc % NSTG;
            if (kc + 2 < NKC) { load_stage((kc + 2) % NSTG, kc + 2); CP_WAIT(2); }
            else if (kc + 1 < NKC) CP_WAIT(1);
            else                   CP_WAIT(0);
            __syncthreads();

            const uint32_t st = sbase + s * STAGEB;
            const uint32_t sA = st, sB = st + SUBT;

#pragma unroll
            for (int ks = 0; ks < 4; ks++) {
                uint32_t a[4][4], b[8][2];
#pragma unroll
                for (int mi = 0; mi < 4; mi++) {
                    uint32_t off = (uint32_t)((wm * 64 + mi * 16 + arow_l) * ROWB + ks * 32 + aseg * 16);
                    LDSM_X4(a[mi][0], a[mi][1], a[mi][2], a[mi][3], sA + off);
                }
#pragma unroll
                for (int np = 0; np < 4; np++) {
                    uint32_t off = (uint32_t)((wn * 64 + np * 16 + brow_l) * ROWB + ks * 32 + bseg * 16);
                    LDSM_X4(b[np*2][0], b[np*2][1], b[np*2+1][0], b[np*2+1][1], sB + off);
                }
#pragma unroll
                for (int mi = 0; mi < 4; mi++)
#pragma unroll
                    for (int nt = 0; nt < 8; nt++)
                        MMA_F16(acc[mi][nt], a[mi], b[nt]);
            }
            __syncthreads();
        }

        // epilogue
#pragma unroll
        for (int mi = 0; mi < 4; mi++) {
            int row = wm * 64 + mi * 16 + g;
#pragma unroll
            for (int nt = 0; nt < 8; nt++) {
                int col = wn * 64 + nt * 8 + tig * 2;
                *(float2*)&Cp[(ll)row * 1024 + col]       = make_float2(acc[mi][nt][0], acc[mi][nt][1]);
                *(float2*)&Cp[(ll)(row + 8) * 1024 + col] = make_float2(acc[mi][nt][2], acc[mi][nt][3]);
            }
        }
    }
}

// ============================ converters ============================
// fp32 -> fp16, vectorized
__global__ __launch_bounds__(256) void convA_h_kernel(const float* __restrict__ x,
                                                      __half* __restrict__ y, int n4)
{
    int i = blockIdx.x * 256 + threadIdx.x;
    if (i >= n4) return;
    float4 v = *(const float4*)&x[(ll)i * 4];
    *(__half2*)&y[(ll)i * 4]     = __floats2half2_rn(v.x, v.y);
    *(__half2*)&y[(ll)i * 4 + 2] = __floats2half2_rn(v.z, v.w);
}

// weight transpose + fp16 convert, batched by blockIdx.z with stride wZ
__global__ __launch_bounds__(1024) void convWT_h_kernel(const float* __restrict__ W,
                                                        __half* __restrict__ y,
                                                        ll wZ)
{
    __shared__ float ts[32][33];
    const ll zo = (ll)blockIdx.z * wZ;
    int tx = threadIdx.x & 31, ty = threadIdx.x >> 5;
    int k0 = blockIdx.y * 32, n0 = blockIdx.x * 32;
    ts[ty][tx] = W[zo + (ll)(k0 + ty) * 1024 + n0 + tx];
    __syncthreads();
    y[zo + (ll)(n0 + ty) * 1024 + k0 + tx] = __float2half_rn(ts[tx][ty]);
}

// ---------------- softmax over 128-wide head slices of Q -> fp16 ----------------
__global__ __launch_bounds__(256) void softmax128_h_kernel(const float* __restrict__ Q,
                                                           __half* __restrict__ out)
{
    ll row = ((ll)blockIdx.x << 3) + (threadIdx.x >> 5);
    int lane = threadIdx.x & 31;
    const float* p = Q + (row << 7);
    float4 v = *(const float4*)&p[lane << 2];
    float m = fmaxf(fmaxf(v.x, v.y), fmaxf(v.z, v.w));
#pragma unroll
    for (int o = 16; o > 0; o >>= 1) m = fmaxf(m, __shfl_xor_sync(0xffffffffu, m, o));
    float4 e;
    e.x = expf(v.x - m); e.y = expf(v.y - m);
    e.z = expf(v.z - m); e.w = expf(v.w - m);
    float s = e.x + e.y + e.z + e.w;
#pragma unroll
    for (int o = 16; o > 0; o >>= 1) s += __shfl_xor_sync(0xffffffffu, s, o);
    float inv = 1.f / s;
    ll o4 = (row << 7) + (lane << 2);
    *(__half2*)&out[o4]     = __floats2half2_rn(e.x * inv, e.y * inv);
    *(__half2*)&out[o4 + 2] = __floats2half2_rn(e.z * inv, e.w * inv);
}

// ---------------- fp32 tiled GEMM (small Z = Kvn @ Wout_h) ----------------
#define BM 128
#define BN 128
#define BK 16
__global__ __launch_bounds__(256) void sgemm_kernel(
    const float* __restrict__ A, const float* __restrict__ Bm, float* __restrict__ C,
    int K, int lda, int ldb, int ldc,
    ll aHi, ll aLo, ll bHi, ll bLo, ll cHi, ll cLo)
{
    const int z = blockIdx.z;
    A  += (ll)(z >> 3) * aHi + (ll)(z & 7) * aLo;
    Bm += (ll)(z >> 3) * bHi + (ll)(z & 7) * bLo;
    C  += (ll)(z >> 3) * cHi + (ll)(z & 7) * cLo;

    __shared__ float As[BK][BM];
    __shared__ float Bs[BK][BN];
    const int tid = threadIdx.x;
    const int ty = tid >> 4, tx = tid & 15;
    const int m0 = blockIdx.y * BM, n0 = blockIdx.x * BN;

    float acc[8][8];
#pragma unroll
    for (int i = 0; i < 8; i++)
#pragma unroll
        for (int j = 0; j < 8; j++) acc[i][j] = 0.f;

    for (int k0 = 0; k0 < K; k0 += BK) {
#pragma unroll
        for (int u = 0; u < 2; u++) {
            int idx = tid + u * 256;
            int r = idx >> 2, c4 = (idx & 3) << 2;
            float4 v = *(const float4*)&A[(ll)(m0 + r) * lda + k0 + c4];
            As[c4 + 0][r] = v.x; As[c4 + 1][r] = v.y;
            As[c4 + 2][r] = v.z; As[c4 + 3][r] = v.w;
        }
#pragma unroll
        for (int u = 0; u < 2; u++) {
            int idx = tid + u * 256;
            int r = idx >> 5, c4 = (idx & 31) << 2;
            *(float4*)&Bs[r][c4] = *(const float4*)&Bm[(ll)(k0 + r) * ldb + n0 + c4];
        }
        __syncthreads();
#pragma unroll
        for (int k = 0; k < BK; k++) {
            float4 a0 = *(const float4*)&As[k][ty * 8];
            float4 a1 = *(const float4*)&As[k][ty * 8 + 4];
            float4 b0 = *(const float4*)&Bs[k][tx * 8];
            float4 b1 = *(const float4*)&Bs[k][tx * 8 + 4];
            float a[8] = {a0.x,a0.y,a0.z,a0.w,a1.x,a1.y,a1.z,a1.w};
            float b[8] = {b0.x,b0.y,b0.z,b0.w,b1.x,b1.y,b1.z,b1.w};
#pragma unroll
            for (int i = 0; i < 8; i++)
#pragma unroll
                for (int j = 0; j < 8; j++) acc[i][j] += a[i] * b[j];
        }
        __syncthreads();
    }
#pragma unroll
    for (int i = 0; i < 8; i++) {
        int r = m0 + ty * 8 + i;
#pragma unroll
        for (int j = 0; j < 8; j += 4) {
            *(float4*)&C[(ll)r * ldc + n0 + tx * 8 + j] =
                make_float4(acc[i][j], acc[i][j+1], acc[i][j+2], acc[i][j+3]);
        }
    }
}

// ---------------- Kv partial over 256-token chunks (fp32) ----------------
__global__ __launch_bounds__(256) void kv_partial_kernel(void)
{
    const int z  = blockIdx.x;
    const int tc = blockIdx.y;
    const int b = z >> 3, h = z & 7;
    const float* Ab = g_K + (ll)b * TT * LATD + h * DHD;
    const float* Bb = g_V + (ll)b * TT * DD   + h * DHD;

    __shared__ float As[16][128];
    __shared__ float Bs[16][128];
    const int tid = threadIdx.x;
    const int ty = tid >> 4, tx = tid & 15;
    float acc[8][8];
#pragma unroll
    for (int i = 0; i < 8; i++)
#pragma unroll
        for (int j = 0; j < 8; j++) acc[i][j] = 0.f;
    float ksum = 0.f;

    const int t0 = tc * TCHUNK;
    for (int tt = 0; tt < TCHUNK; tt += 16) {
#pragma unroll
        for (int u = 0; u < 2; u++) {
            int idx = tid + u * 256;
            int k = idx >> 5, i4 = (idx & 31) << 2;
            ll trow = (ll)(t0 + tt + k);
            float4 va = *(const float4*)&Ab[trow * LATD + i4];
            As[k][i4 + 0] = expf(va.x); As[k][i4 + 1] = expf(va.y);
            As[k][i4 + 2] = expf(va.z); As[k][i4 + 3] = expf(va.w);
            *(float4*)&Bs[k][i4] = *(const float4*)&Bb[trow * DD + i4];
        }
        __syncthreads();
        if (tid < 128) {
#pragma unroll
            for (int k = 0; k < 16; k++) ksum += As[k][tid];
        }
#pragma unroll
        for (int k = 0; k < 16; k++) {
            float4 a0 = *(const float4*)&As[k][ty * 8];
            float4 a1 = *(const float4*)&As[k][ty * 8 + 4];
            float4 b0 = *(const float4*)&Bs[k][tx * 8];
            float4 b1 = *(const float4*)&Bs[k][tx * 8 + 4];
            float a[8] = {a0.x,a0.y,a0.z,a0.w,a1.x,a1.y,a1.z,a1.w};
            float b[8] = {b0.x,b0.y,b0.z,b0.w,b1.x,b1.y,b1.z,b1.w};
#pragma unroll
            for (int i = 0; i < 8; i++)
#pragma unroll
                for (int j = 0; j < 8; j++) acc[i][j] += a[i] * b[j];
        }
        __syncthreads();
    }

    float* Cp = g_Kvpart + ((ll)tc * 32 + z) * (128 * 128);
#pragma unroll
    for (int i = 0; i < 8; i++) {
        int r = ty * 8 + i;
#pragma unroll
        for (int j = 0; j < 8; j += 4) {
            *(float4*)&Cp[r * 128 + tx * 8 + j] =
                make_float4(acc[i][j], acc[i][j+1], acc[i][j+2], acc[i][j+3]);
        }
    }
    if (tid < 128) g_Ksumpart[((ll)tc * 32 + z) * 128 + tid] = ksum;
}

__global__ __launch_bounds__(128) void kv_reduce_norm_kernel(void)
{
    const int j  = threadIdx.x;
    const int zi = blockIdx.x;
    const int z = zi >> 7, i = zi & 127;
    float kv = 0.f, s = 0.f;
#pragma unroll
    for (int tc = 0; tc < TSPLIT; tc++) {
        kv += g_Kvpart[((ll)tc * 32 + z) * 16384 + i * 128 + j];
        s  += g_Ksumpart[((ll)tc * 32 + z) * 128 + i];
    }
    g_Kvn[(ll)z * 16384 + i * 128 + j] = kv / s;
}

// ---------------- launch ----------------
extern "C" void kernel_launch(void* const* d_in, const int* in_sizes, int n_in,
                              void* d_out, int out_size)
{
    const float* query = (const float*)d_in[0];
    const float* key   = (const float*)d_in[1];
    const float* wq    = (const float*)d_in[2];
    const float* wk    = (const float*)d_in[3];
    const float* wv    = (const float*)d_in[4];
    const float* wproj = (const float*)d_in[5];
    float* out = (float*)d_out;

    float *Q, *K, *V, *Z, *Kvn;
    __half *Aq, *Ak, *Bw;
    cudaGetSymbolAddress((void**)&Q,   g_Q);
    cudaGetSymbolAddress((void**)&K,   g_K);
    cudaGetSymbolAddress((void**)&V,   g_V);
    cudaGetSymbolAddress((void**)&Z,   g_Z);
    cudaGetSymbolAddress((void**)&Kvn, g_Kvn);
    cudaGetSymbolAddress((void**)&Aq,  g_Aq);
    cudaGetSymbolAddress((void**)&Ak,  g_Ak);
    cudaGetSymbolAddress((void**)&Bw,  g_Bw);

    cudaFuncSetAttribute(phmma_kernel, cudaFuncAttributeMaxDynamicSharedMemorySize, GEMM_SMEM);

    int nsm = 148;
    cudaDeviceGetAttribute(&nsm, cudaDevAttrMultiProcessorCount, 0);
    const int pgrid = nsm * 2;

    const int MBT = BATCH * TT;                 // 16384
    const int actN4 = MBT * DD / 4;
    dim3 gconvA((actN4 + 255) / 256), bconvA(256);
    dim3 gconvW(32, 32, 1), bconvW(1024);

    // ---- converts: activations + transposed weights, all single fp16 ----
    convA_h_kernel<<<gconvA, bconvA>>>(query, Aq, actN4);
    convA_h_kernel<<<gconvA, bconvA>>>(key,   Ak, actN4);
    convWT_h_kernel<<<gconvW, bconvW>>>(wq, Bw + 0ll * 1048576, 0);
    convWT_h_kernel<<<gconvW, bconvW>>>(wk, Bw + 1ll * 1048576, 0);
    convWT_h_kernel<<<gconvW, bconvW>>>(wv, Bw + 2ll * 1048576, 0);

    // ---- persistent QKV mega-GEMM (3 x 1024 tiles) ----
    GemmJobs jq;
    jq.A[0] = Aq;  jq.A[1] = Ak;  jq.A[2] = Ak;
    jq.B[0] = Bw;  jq.B[1] = Bw + 1048576; jq.B[2] = Bw + 2097152;
    jq.C[0] = Q;   jq.C[1] = K;   jq.C[2] = V;
    jq.total = 3072; jq.bShift = -1; jq.bStride = 0;
    phmma_kernel<<<pgrid, 128, GEMM_SMEM>>>(jq);

    // ---- softmax(Q) -> fp16 into Aq ----
    softmax128_h_kernel<<<(MBT * NH) / 8, 256>>>(Q, Aq);

    // ---- Kv aggregation + normalize -> Kvn ----
    kv_partial_kernel<<<dim3(32, TSPLIT, 1), 256>>>();
    kv_reduce_norm_kernel<<<dim3(32 * 128, 1, 1), 128>>>();

    // ---- Z[b, h*128+l, n] = sum_d Kvn[b,h,l,d] * Wout[h*128+d, n] ----
    dim3 gz(8, 1, 32);
    sgemm_kernel<<<gz, 256>>>(Kvn, wproj, Z, 128, 128, 1024, 1024,
                              (ll)8 * 16384, 16384,
                              0, 131072,
                              1048576, 131072);

    // ---- convert Z (4 batches) -> Bw, then persistent OUT GEMM ----
    dim3 gconvWZ(32, 32, 4);
    convWT_h_kernel<<<gconvWZ, bconvW>>>(Z, Bw, 1048576);

    GemmJobs jo;
    jo.A[0] = Aq;  jo.A[1] = Aq;  jo.A[2] = Aq;
    jo.B[0] = Bw;  jo.B[1] = Bw;  jo.B[2] = Bw;
    jo.C[0] = out; jo.C[1] = out; jo.C[2] = out;
    jo.total = 1024; jo.bShift = 5; jo.bStride = 1048576;   // b = m_idx>>5
    phmma_kernel<<<pgrid, 128, GEMM_SMEM>>>(jo);
}

// round 11
// speedup vs baseline: 2.3522x; 1.1452x over previous
#include <cuda_runtime.h>
#include <cuda_fp16.h>
#include <math.h>
#include <stdint.h>

// Problem constants
#define BATCH 4
#define TT    4096
#define DD    1024
#define LATD  1024
#define NH    8
#define DHD   128

typedef long long ll;

// ---------------- scratch (device globals; no allocation allowed) ----------------
__device__ float g_Q[(size_t)BATCH * TT * LATD];
__device__ float g_Z[(size_t)BATCH * DD * DD];
__device__ float g_Kvpart[(size_t)8 * 32 * 128 * 128];    // [tc][z][i][j]
__device__ float g_Ksumpart[(size_t)32 * 32 * 128];       // [ch][z][i]
__device__ float g_Kvn[(size_t)32 * 128 * 128];
// fp16 buffers
__device__ __half g_Aq[(size_t)BATCH * TT * DD];   // query fp16, later softmax(Q) fp16
__device__ __half g_Ak[(size_t)BATCH * TT * DD];   // key fp16
__device__ __half g_Bw[(size_t)4 * DD * DD];       // weight^T fp16: wq,wk,wv | Z(4 batches)
__device__ __half g_eK[(size_t)BATCH * TT * DD];   // exp(K) fp16 [b][t][1024]
__device__ __half g_Vh[(size_t)BATCH * TT * DD];   // V fp16 [b][t][1024]

// ============================ PTX helpers ============================
__device__ __forceinline__ uint32_t smem_u32(const void* p) {
    uint32_t a;
    asm("{ .reg .u64 t; cvta.to.shared.u64 t, %1; cvt.u32.u64 %0, t; }" : "=r"(a) : "l"(p));
    return a;
}
#define CP_ASYNC16(s, g) asm volatile("cp.async.cg.shared.global [%0], [%1], 16;" :: "r"(s), "l"(g))
#define CP_COMMIT() asm volatile("cp.async.commit_group;" ::: "memory")
#define CP_WAIT(n)  asm volatile("cp.async.wait_group %0;" :: "n"(n) : "memory")

#define LDSM_X4(r0, r1, r2, r3, a) \
    asm volatile("ldmatrix.sync.aligned.m8n8.x4.shared.b16 {%0,%1,%2,%3}, [%4];" \
                 : "=r"(r0), "=r"(r1), "=r"(r2), "=r"(r3) : "r"(a))

#define LDSM_X4_T(r0, r1, r2, r3, a) \
    asm volatile("ldmatrix.sync.aligned.m8n8.x4.trans.shared.b16 {%0,%1,%2,%3}, [%4];" \
                 : "=r"(r0), "=r"(r1), "=r"(r2), "=r"(r3) : "r"(a))

#define MMA_F16(c, a, b) \
    asm volatile("mma.sync.aligned.m16n8k16.row.col.f32.f16.f16.f32 " \
                 "{%0,%1,%2,%3}, {%4,%5,%6,%7}, {%8,%9}, {%0,%1,%2,%3};" \
                 : "+f"((c)[0]), "+f"((c)[1]), "+f"((c)[2]), "+f"((c)[3]) \
                 : "r"((a)[0]), "r"((a)[1]), "r"((a)[2]), "r"((a)[3]), \
                   "r"((b)[0]), "r"((b)[1]))

// ============================ persistent single-fp16 HMMA GEMM ============================
// C_tile[128,128] = A[128rows,K=1024] x B[128rows,K=1024]^T   (B N-major "col")
// Tile 128x128, 4 warps (64x64 each), K-chunk 64, 3-stage cp.async, 2 CTAs/SM.
// Per-job epilogue: 0 = fp32, 1 = fp16 exp(), 2 = fp16.
#define NKC 16
#define ROWB 144                 // 128B data + 16B pad
#define SUBT (128 * ROWB)        // 18432
#define STAGEB (2 * SUBT)        // A, B = 36864
#define NSTG 3
#define GEMM_SMEM (NSTG * STAGEB)   // 110592

struct GemmJobs {
    const __half* A[3];
    const __half* B[3];
    void*         C[3];
    int           epi[3];
    int total;       // total tiles (njobs * 1024)
    int bShift;      // -1, or m_idx>>bShift selects B batch
    ll  bStride;     // element stride between B batches
};

__global__ __launch_bounds__(128, 2) void phmma_kernel(GemmJobs J)
{
    extern __shared__ char dsm[];
    const uint32_t sbase = smem_u32(dsm);
    const int tid = threadIdx.x;
    const int wid = tid >> 5, lane = tid & 31;
    const int wm = wid & 1, wn = wid >> 1;
    const int arow_l = lane & 15, aseg = lane >> 4;
    const int brow_l = (lane & 7) + ((lane >> 4) << 3), bseg = (lane >> 3) & 1;
    const int g = lane >> 2, tig = lane & 3;

    for (int t = blockIdx.x; t < J.total; t += gridDim.x) {
        const int job = t >> 10;            // 1024 tiles per job
        const int rem = t & 1023;
        const int mI = rem >> 3, nI = rem & 7;

        const __half* Ap = J.A[job] + (ll)mI * 131072;
        const __half* Bp = J.B[job];
        if (J.bShift >= 0) Bp += (ll)(mI >> J.bShift) * J.bStride;
        Bp += (ll)nI * 131072;
        const ll cOff = (ll)mI * 131072 + nI * 128;

        float acc[4][8][4];
#pragma unroll
        for (int i = 0; i < 4; i++)
#pragma unroll
            for (int j = 0; j < 8; j++)
#pragma unroll
                for (int v = 0; v < 4; v++) acc[i][j][v] = 0.f;

        auto load_stage = [&](int s, int kc) {
            uint32_t st = sbase + s * STAGEB;
            const int k0 = kc * 64;
            const __half* gs[2] = { Ap + k0, Bp + k0 };
#pragma unroll
            for (int sub = 0; sub < 2; sub++) {
                const __half* gg = gs[sub];
                uint32_t base = st + sub * SUBT;
#pragma unroll
                for (int u = 0; u < 8; u++) {
                    int idx = tid + u * 128;      // 0..1023
                    int r = idx >> 3, ch = idx & 7;
                    CP_ASYNC16(base + r * ROWB + ch * 16, gg + (ll)r * 1024 + ch * 8);
                }
            }
            CP_COMMIT();
        };

        load_stage(0, 0);
        load_stage(1, 1);
        for (int kc = 0; kc < NKC; kc++) {
            const int s = kc % NSTG;
            if (kc + 2 < NKC) { load_stage((kc + 2) % NSTG, kc + 2); CP_WAIT(2); }
            else if (kc + 1 < NKC) CP_WAIT(1);
            else                   CP_WAIT(0);
            __syncthreads();

            const uint32_t st = sbase + s * STAGEB;
            const uint32_t sA = st, sB = st + SUBT;

#pragma unroll
            for (int ks = 0; ks < 4; ks++) {
                uint32_t a[4][4], b[8][2];
#pragma unroll
                for (int mi = 0; mi < 4; mi++) {
                    uint32_t off = (uint32_t)((wm * 64 + mi * 16 + arow_l) * ROWB + ks * 32 + aseg * 16);
                    LDSM_X4(a[mi][0], a[mi][1], a[mi][2], a[mi][3], sA + off);
                }
#pragma unroll
                for (int np = 0; np < 4; np++) {
                    uint32_t off = (uint32_t)((wn * 64 + np * 16 + brow_l) * ROWB + ks * 32 + bseg * 16);
                    LDSM_X4(b[np*2][0], b[np*2][1], b[np*2+1][0], b[np*2+1][1], sB + off);
                }
#pragma unroll
                for (int mi = 0; mi < 4; mi++)
#pragma unroll
                    for (int nt = 0; nt < 8; nt++)
                        MMA_F16(acc[mi][nt], a[mi], b[nt]);
            }
            __syncthreads();
        }

        // epilogue (per-job mode)
        const int ep = J.epi[job];
        if (ep == 0) {
            float* Cf = (float*)J.C[job] + cOff;
#pragma unroll
            for (int mi = 0; mi < 4; mi++) {
                int row = wm * 64 + mi * 16 + g;
#pragma unroll
                for (int nt = 0; nt < 8; nt++) {
                    int col = wn * 64 + nt * 8 + tig * 2;
                    *(float2*)&Cf[(ll)row * 1024 + col]       = make_float2(acc[mi][nt][0], acc[mi][nt][1]);
                    *(float2*)&Cf[(ll)(row + 8) * 1024 + col] = make_float2(acc[mi][nt][2], acc[mi][nt][3]);
                }
            }
        } else {
            __half* Ch = (__half*)J.C[job] + cOff;
#pragma unroll
            for (int mi = 0; mi < 4; mi++) {
                int row = wm * 64 + mi * 16 + g;
#pragma unroll
                for (int nt = 0; nt < 8; nt++) {
                    int col = wn * 64 + nt * 8 + tig * 2;
                    float a0 = acc[mi][nt][0], a1 = acc[mi][nt][1];
                    float a2 = acc[mi][nt][2], a3 = acc[mi][nt][3];
                    if (ep == 1) { a0 = expf(a0); a1 = expf(a1); a2 = expf(a2); a3 = expf(a3); }
                    *(__half2*)&Ch[(ll)row * 1024 + col]       = __floats2half2_rn(a0, a1);
                    *(__half2*)&Ch[(ll)(row + 8) * 1024 + col] = __floats2half2_rn(a2, a3);
                }
            }
        }
    }
}

// ============================ kv fp16 HMMA: Kvpart[tc][z] = expK^T x V over 512 t ============================
// A[i][t] from g_eK stored [t][i] via ldmatrix.trans; B[j][t] from g_Vh stored [t][j] via trans.
// Tile 128x128, 4 warps (64x64), k-chunk 64 t, 8 chunks, 3-stage cp.async.
#define KPITCH 272               // 256B data + 16B pad (non-128 multiple => trans-ldsm conflict-free)
#define KSUBT (64 * KPITCH)      // 17408
#define KSTAGEB (2 * KSUBT)      // 34816
#define KV_SMEM (NSTG * KSTAGEB) // 104448

__global__ __launch_bounds__(128, 2) void kv16_kernel(void)
{
    extern __shared__ char dsm[];
    const uint32_t sbase = smem_u32(dsm);
    const int tid = threadIdx.x;
    const int wid = tid >> 5, lane = tid & 31;
    const int wm = wid & 1, wn = wid >> 1;
    const int z = blockIdx.x, tc = blockIdx.y;
    const int b = z >> 3, h = z & 7;

    // trans-ldsm lane patterns (derived from non-trans fragment order + transpose semantics)
    const int asrow = (lane & 7) + ((lane >> 4) << 3);        // A: +8 k rows via bit4
    const int ascol = ((lane >> 3) & 1) * 8;                  //    +8 i cols via bit3
    const int bsrow = (lane & 7) + (((lane >> 3) & 1) << 3);  // B: +8 k rows via bit3
    const int bscol = (lane >> 4) * 8;                        //    +8 j cols via bit4
    const int g = lane >> 2, tig = lane & 3;

    const __half* Ag = g_eK + (ll)b * TT * DD + h * DHD;   // [t][i], row pitch 1024
    const __half* Bg = g_Vh + (ll)b * TT * DD + h * DHD;   // [t][j]
    const int tbase = tc * 512;

    float acc[4][8][4];
#pragma unroll
    for (int i = 0; i < 4; i++)
#pragma unroll
        for (int j = 0; j < 8; j++)
#pragma unroll
            for (int v = 0; v < 4; v++) acc[i][j][v] = 0.f;

    auto load_stage = [&](int s, int kc) {
        uint32_t st = sbase + s * KSTAGEB;
        const int t0 = tbase + kc * 64;
        const __half* gs[2] = { Ag, Bg };
#pragma unroll
        for (int sub = 0; sub < 2; sub++) {
            const __half* gg = gs[sub];
            uint32_t base = st + sub * KSUBT;
#pragma unroll
            for (int u = 0; u < 8; u++) {
                int idx = tid + u * 128;         // 0..1023: 64 rows x 16 chunks
                int r = idx >> 4, c = idx & 15;
                CP_ASYNC16(base + r * KPITCH + c * 16, gg + (ll)(t0 + r) * 1024 + c * 8);
            }
        }
        CP_COMMIT();
    };

    load_stage(0, 0);
    load_stage(1, 1);
    for (int kc = 0; kc < 8; kc++) {
        const int s = kc % NSTG;
        if (kc + 2 < 8) { load_stage((kc + 2) % NSTG, kc + 2); CP_WAIT(2); }
        else if (kc + 1 < 8) CP_WAIT(1);
        else                 CP_WAIT(0);
        __syncthreads();

        const uint32_t st = sbase + s * KSTAGEB;
        const uint32_t sA = st, sB = st + KSUBT;

#pragma unroll
        for (int ks = 0; ks < 4; ks++) {
            uint32_t a[4][4], bf[8][2];
#pragma unroll
            for (int mi = 0; mi < 4; mi++) {
                int i0 = wm * 64 + mi * 16;
                uint32_t off = (uint32_t)((ks * 16 + asrow) * KPITCH + (i0 + ascol) * 2);
                LDSM_X4_T(a[mi][0], a[mi][1], a[mi][2], a[mi][3], sA + off);
            }
#pragma unroll
            for (int np = 0; np < 4; np++) {
                int j0 = wn * 64 + np * 16;
                uint32_t off = (uint32_t)((ks * 16 + bsrow) * KPITCH + (j0 + bscol) * 2);
                LDSM_X4_T(bf[np*2][0], bf[np*2][1], bf[np*2+1][0], bf[np*2+1][1], sB + off);
            }
#pragma unroll
            for (int mi = 0; mi < 4; mi++)
#pragma unroll
                for (int nt = 0; nt < 8; nt++)
                    MMA_F16(acc[mi][nt], a[mi], bf[nt]);
        }
        __syncthreads();
    }

    float* Cp = g_Kvpart + ((ll)tc * 32 + z) * 16384;
#pragma unroll
    for (int mi = 0; mi < 4; mi++) {
        int row = wm * 64 + mi * 16 + g;
#pragma unroll
        for (int nt = 0; nt < 8; nt++) {
            int col = wn * 64 + nt * 8 + tig * 2;
            *(float2*)&Cp[row * 128 + col]       = make_float2(acc[mi][nt][0], acc[mi][nt][1]);
            *(float2*)&Cp[(row + 8) * 128 + col] = make_float2(acc[mi][nt][2], acc[mi][nt][3]);
        }
    }
}

// ---------------- Ksum partials from g_eK (fp16-consistent with kv numerator) ----------------
__global__ __launch_bounds__(128) void ksum_kernel(void)
{
    const int z = blockIdx.x, ch = blockIdx.y;   // 32 z x 32 chunks of 128 t
    const int b = z >> 3, h = z & 7;
    const __half* p = g_eK + (ll)b * TT * DD + h * DHD + threadIdx.x;
    float s = 0.f;
    const int t0 = ch * 128;
    for (int t = 0; t < 128; t++)
        s += __half2float(p[(ll)(t0 + t) * 1024]);
    g_Ksumpart[((ll)ch * 32 + z) * 128 + threadIdx.x] = s;
}

// ---------------- reduce + normalize ----------------
__global__ __launch_bounds__(128) void kv_reduce_norm_kernel(void)
{
    const int j  = threadIdx.x;
    const int zi = blockIdx.x;
    const int z = zi >> 7, i = zi & 127;
    float kv = 0.f, s = 0.f;
#pragma unroll
    for (int tc = 0; tc < 8; tc++)
        kv += g_Kvpart[((ll)tc * 32 + z) * 16384 + i * 128 + j];
#pragma unroll
    for (int ch = 0; ch < 32; ch++)
        s += g_Ksumpart[((ll)ch * 32 + z) * 128 + i];
    g_Kvn[(ll)z * 16384 + i * 128 + j] = kv / s;
}

// ============================ converters ============================
__global__ __launch_bounds__(256) void convA_h_kernel(const float* __restrict__ x,
                                                      __half* __restrict__ y, int n4)
{
    int i = blockIdx.x * 256 + threadIdx.x;
    if (i >= n4) return;
    float4 v = *(const float4*)&x[(ll)i * 4];
    *(__half2*)&y[(ll)i * 4]     = __floats2half2_rn(v.x, v.y);
    *(__half2*)&y[(ll)i * 4 + 2] = __floats2half2_rn(v.z, v.w);
}

__global__ __launch_bounds__(1024) void convWT_h_kernel(const float* __restrict__ W,
                                                        __half* __restrict__ y,
                                                        ll wZ)
{
    __shared__ float ts[32][33];
    const ll zo = (ll)blockIdx.z * wZ;
    int tx = threadIdx.x & 31, ty = threadIdx.x >> 5;
    int k0 = blockIdx.y * 32, n0 = blockIdx.x * 32;
    ts[ty][tx] = W[zo + (ll)(k0 + ty) * 1024 + n0 + tx];
    __syncthreads();
    y[zo + (ll)(n0 + ty) * 1024 + k0 + tx] = __float2half_rn(ts[tx][ty]);
}

// ---------------- softmax over 128-wide head slices of Q -> fp16 ----------------
__global__ __launch_bounds__(256) void softmax128_h_kernel(const float* __restrict__ Q,
                                                           __half* __restrict__ out)
{
    ll row = ((ll)blockIdx.x << 3) + (threadIdx.x >> 5);
    int lane = threadIdx.x & 31;
    const float* p = Q + (row << 7);
    float4 v = *(const float4*)&p[lane << 2];
    float m = fmaxf(fmaxf(v.x, v.y), fmaxf(v.z, v.w));
#pragma unroll
    for (int o = 16; o > 0; o >>= 1) m = fmaxf(m, __shfl_xor_sync(0xffffffffu, m, o));
    float4 e;
    e.x = expf(v.x - m); e.y = expf(v.y - m);
    e.z = expf(v.z - m); e.w = expf(v.w - m);
    float s = e.x + e.y + e.z + e.w;
#pragma unroll
    for (int o = 16; o > 0; o >>= 1) s += __shfl_xor_sync(0xffffffffu, s, o);
    float inv = 1.f / s;
    ll o4 = (row << 7) + (lane << 2);
    *(__half2*)&out[o4]     = __floats2half2_rn(e.x * inv, e.y * inv);
    *(__half2*)&out[o4 + 2] = __floats2half2_rn(e.z * inv, e.w * inv);
}

// ---------------- fp32 tiled GEMM (small Z = Kvn @ Wout_h) ----------------
#define BM 128
#define BN 128
#define BK 16
__global__ __launch_bounds__(256) void sgemm_kernel(
    const float* __restrict__ A, const float* __restrict__ Bm, float* __restrict__ C,
    int K, int lda, int ldb, int ldc,
    ll aHi, ll aLo, ll bHi, ll bLo, ll cHi, ll cLo)
{
    const int z = blockIdx.z;
    A  += (ll)(z >> 3) * aHi + (ll)(z & 7) * aLo;
    Bm += (ll)(z >> 3) * bHi + (ll)(z & 7) * bLo;
    C  += (ll)(z >> 3) * cHi + (ll)(z & 7) * cLo;

    __shared__ float As[BK][BM];
    __shared__ float Bs[BK][BN];
    const int tid = threadIdx.x;
    const int ty = tid >> 4, tx = tid & 15;
    const int m0 = blockIdx.y * BM, n0 = blockIdx.x * BN;

    float acc[8][8];
#pragma unroll
    for (int i = 0; i < 8; i++)
#pragma unroll
        for (int j = 0; j < 8; j++) acc[i][j] = 0.f;

    for (int k0 = 0; k0 < K; k0 += BK) {
#pragma unroll
        for (int u = 0; u < 2; u++) {
            int idx = tid + u * 256;
            int r = idx >> 2, c4 = (idx & 3) << 2;
            float4 v = *(const float4*)&A[(ll)(m0 + r) * lda + k0 + c4];
            As[c4 + 0][r] = v.x; As[c4 + 1][r] = v.y;
            As[c4 + 2][r] = v.z; As[c4 + 3][r] = v.w;
        }
#pragma unroll
        for (int u = 0; u < 2; u++) {
            int idx = tid + u * 256;
            int r = idx >> 5, c4 = (idx & 31) << 2;
            *(float4*)&Bs[r][c4] = *(const float4*)&Bm[(ll)(k0 + r) * ldb + n0 + c4];
        }
        __syncthreads();
#pragma unroll
        for (int k = 0; k < BK; k++) {
            float4 a0 = *(const float4*)&As[k][ty * 8];
            float4 a1 = *(const float4*)&As[k][ty * 8 + 4];
            float4 b0 = *(const float4*)&Bs[k][tx * 8];
            float4 b1 = *(const float4*)&Bs[k][tx * 8 + 4];
            float a[8] = {a0.x,a0.y,a0.z,a0.w,a1.x,a1.y,a1.z,a1.w};
            float b[8] = {b0.x,b0.y,b0.z,b0.w,b1.x,b1.y,b1.z,b1.w};
#pragma unroll
            for (int i = 0; i < 8; i++)
#pragma unroll
                for (int j = 0; j < 8; j++) acc[i][j] += a[i] * b[j];
        }
        __syncthreads();
    }
#pragma unroll
    for (int i = 0; i < 8; i++) {
        int r = m0 + ty * 8 + i;
#pragma unroll
        for (int j = 0; j < 8; j += 4) {
            *(float4*)&C[(ll)r * ldc + n0 + tx * 8 + j] =
                make_float4(acc[i][j], acc[i][j+1], acc[i][j+2], acc[i][j+3]);
        }
    }
}

// ---------------- launch ----------------
extern "C" void kernel_launch(void* const* d_in, const int* in_sizes, int n_in,
                              void* d_out, int out_size)
{
    const float* query = (const float*)d_in[0];
    const float* key   = (const float*)d_in[1];
    const float* wq    = (const float*)d_in[2];
    const float* wk    = (const float*)d_in[3];
    const float* wv    = (const float*)d_in[4];
    const float* wproj = (const float*)d_in[5];
    float* out = (float*)d_out;

    float *Q, *Z, *Kvn;
    __half *Aq, *Ak, *Bw, *eK, *Vh;
    cudaGetSymbolAddress((void**)&Q,   g_Q);
    cudaGetSymbolAddress((void**)&Z,   g_Z);
    cudaGetSymbolAddress((void**)&Kvn, g_Kvn);
    cudaGetSymbolAddress((void**)&Aq,  g_Aq);
    cudaGetSymbolAddress((void**)&Ak,  g_Ak);
    cudaGetSymbolAddress((void**)&Bw,  g_Bw);
    cudaGetSymbolAddress((void**)&eK,  g_eK);
    cudaGetSymbolAddress((void**)&Vh,  g_Vh);

    cudaFuncSetAttribute(phmma_kernel, cudaFuncAttributeMaxDynamicSharedMemorySize, GEMM_SMEM);
    cudaFuncSetAttribute(kv16_kernel,  cudaFuncAttributeMaxDynamicSharedMemorySize, KV_SMEM);

    int nsm = 148;
    cudaDeviceGetAttribute(&nsm, cudaDevAttrMultiProcessorCount, 0);
    const int pgrid = nsm * 2;

    const int MBT = BATCH * TT;                 // 16384
    const int actN4 = MBT * DD / 4;
    dim3 gconvA((actN4 + 255) / 256), bconvA(256);
    dim3 gconvW(32, 32, 1), bconvW(1024);

    // ---- converts ----
    convA_h_kernel<<<gconvA, bconvA>>>(query, Aq, actN4);
    convA_h_kernel<<<gconvA, bconvA>>>(key,   Ak, actN4);
    convWT_h_kernel<<<gconvW, bconvW>>>(wq, Bw + 0ll * 1048576, 0);
    convWT_h_kernel<<<gconvW, bconvW>>>(wk, Bw + 1ll * 1048576, 0);
    convWT_h_kernel<<<gconvW, bconvW>>>(wv, Bw + 2ll * 1048576, 0);

    // ---- persistent QKV mega-GEMM: Q fp32 | exp(K) fp16 | V fp16 ----
    GemmJobs jq;
    jq.A[0] = Aq;  jq.A[1] = Ak;  jq.A[2] = Ak;
    jq.B[0] = Bw;  jq.B[1] = Bw + 1048576; jq.B[2] = Bw + 2097152;
    jq.C[0] = Q;   jq.C[1] = eK;  jq.C[2] = Vh;
    jq.epi[0] = 0; jq.epi[1] = 1; jq.epi[2] = 2;
    jq.total = 3072; jq.bShift = -1; jq.bStride = 0;
    phmma_kernel<<<pgrid, 128, GEMM_SMEM>>>(jq);

    // ---- softmax(Q) -> fp16 into Aq ----
    softmax128_h_kernel<<<(MBT * NH) / 8, 256>>>(Q, Aq);

    // ---- kv aggregation (fp16 HMMA) + Ksum + reduce/normalize ----
    kv16_kernel<<<dim3(32, 8), 128, KV_SMEM>>>();
    ksum_kernel<<<dim3(32, 32), 128>>>();
    kv_reduce_norm_kernel<<<dim3(32 * 128), 128>>>();

    // ---- Z[b, h*128+l, n] = sum_d Kvn[b,h,l,d] * Wout[h*128+d, n] ----
    dim3 gz(8, 1, 32);
    sgemm_kernel<<<gz, 256>>>(Kvn, wproj, Z, 128, 128, 1024, 1024,
                              (ll)8 * 16384, 16384,
                              0, 131072,
                              1048576, 131072);

    // ---- convert Z (4 batches) -> Bw, then persistent OUT GEMM ----
    dim3 gconvWZ(32, 32, 4);
    convWT_h_kernel<<<gconvWZ, bconvW>>>(Z, Bw, 1048576);

    GemmJobs jo;
    jo.A[0] = Aq;  jo.A[1] = Aq;  jo.A[2] = Aq;
    jo.B[0] = Bw;  jo.B[1] = Bw;  jo.B[2] = Bw;
    jo.C[0] = out; jo.C[1] = out; jo.C[2] = out;
    jo.epi[0] = 0; jo.epi[1] = 0; jo.epi[2] = 0;
    jo.total = 1024; jo.bShift = 5; jo.bStride = 1048576;   // b = m_idx>>5
    phmma_kernel<<<pgrid, 128, GEMM_SMEM>>>(jo);
}